// round 1
// baseline (speedup 1.0000x reference)
#include <cuda_runtime.h>
#include <math.h>

#define Hdim 1024
#define Bdim 2
#define Sdim 4096
#define MTOT (Bdim*Sdim)   // 8192
#define TOPK 4
#define INV_SCALE 0.125f   // 1/sqrt(64)
#define LNEPS 1e-5f

// ---------------- scratch (device globals: allowed) ----------------
__device__ float g_q[MTOT*Hdim];
__device__ float g_k[MTOT*Hdim];
__device__ float g_v[MTOT*Hdim];
__device__ float g_logits[(long)Bdim*Sdim*Sdim];   // 128 MB
__device__ float g_topv[MTOT*TOPK];
__device__ int   g_topi[MTOT*TOPK];
__device__ float g_routed[MTOT*Hdim];
__device__ float g_cpre[MTOT*Hdim];
__device__ float g_combined[MTOT*Hdim];
__device__ float g_hpre[MTOT*Hdim];
__device__ float g_h[MTOT*Hdim];

// ---------------- SGEMM: 128x128 block tile, BK=16, 256 thr, 8x8 ----------------
#define BM 128
#define BN 128
#define BK 16
#define TM 8
#define TN 8

// MODE 0: C = acc + bias[n]          (NN)
// MODE 1: C += acc                   (NN, accumulate)
// MODE 2: C = acc * alpha            (NT: B is [N,K] row-major)
// MODE 3: g = sigmoid(acc+bias); C = g*E1 + (1-g)*E2   (NN)
template<int MODE>
__global__ void __launch_bounds__(256)
sgemm128(const float* __restrict__ A, const float* __restrict__ Bmat,
         const float* __restrict__ bias,
         const float* __restrict__ E1, const float* __restrict__ E2,
         float* __restrict__ C,
         int K, int N,
         long strideA, long strideB, long strideC,
         float alpha)
{
    __shared__ float As[BK][BM];
    __shared__ float Bs[BK][BN];

    const int bx = blockIdx.x;   // n tile
    const int by = blockIdx.y;   // m tile
    const int tid = threadIdx.x;
    const int tx = tid & 15;
    const int ty = tid >> 4;

    const float* Ab = A + blockIdx.z * strideA + (long)by * BM * K;
    const float* Bb;
    if (MODE == 2) Bb = Bmat + blockIdx.z * strideB + (long)bx * BN * K;
    else           Bb = Bmat + (long)bx * BN;

    float acc[TM][TN];
#pragma unroll
    for (int i = 0; i < TM; i++)
#pragma unroll
        for (int j = 0; j < TN; j++) acc[i][j] = 0.f;

    for (int k0 = 0; k0 < K; k0 += BK) {
        // A tile: 128 rows x 16 cols, transposed into As[k][m]
#pragma unroll
        for (int l = 0; l < 2; l++) {
            int id = tid + l * 256;
            int r  = id >> 2;
            int c4 = (id & 3) * 4;
            float4 va = *reinterpret_cast<const float4*>(Ab + (long)r * K + k0 + c4);
            As[c4 + 0][r] = va.x; As[c4 + 1][r] = va.y;
            As[c4 + 2][r] = va.z; As[c4 + 3][r] = va.w;
        }
        if (MODE == 2) {
            // B tile from [N,K] rows: transpose into Bs[k][n]
#pragma unroll
            for (int l = 0; l < 2; l++) {
                int id = tid + l * 256;
                int r  = id >> 2;
                int c4 = (id & 3) * 4;
                float4 vb = *reinterpret_cast<const float4*>(Bb + (long)r * K + k0 + c4);
                Bs[c4 + 0][r] = vb.x; Bs[c4 + 1][r] = vb.y;
                Bs[c4 + 2][r] = vb.z; Bs[c4 + 3][r] = vb.w;
            }
        } else {
            // B tile from [K,N]: 16 rows x 128 cols, direct
#pragma unroll
            for (int l = 0; l < 2; l++) {
                int id = tid + l * 256;
                int r  = id >> 5;
                int c  = (id & 31) * 4;
                float4 vb = *reinterpret_cast<const float4*>(Bb + (long)(k0 + r) * N + c);
                *reinterpret_cast<float4*>(&Bs[r][c]) = vb;
            }
        }
        __syncthreads();

#pragma unroll
        for (int kk = 0; kk < BK; kk++) {
            float a[TM], b[TN];
#pragma unroll
            for (int i = 0; i < TM; i++) a[i] = As[kk][ty * TM + i];
#pragma unroll
            for (int j = 0; j < TN; j++) b[j] = Bs[kk][tx * TN + j];
#pragma unroll
            for (int i = 0; i < TM; i++)
#pragma unroll
                for (int j = 0; j < TN; j++)
                    acc[i][j] = fmaf(a[i], b[j], acc[i][j]);
        }
        __syncthreads();
    }

    const long cbase = blockIdx.z * strideC;
#pragma unroll
    for (int i = 0; i < TM; i++) {
        int m = by * BM + ty * TM + i;
#pragma unroll
        for (int j = 0; j < TN; j++) {
            int n = bx * BN + tx * TN + j;
            long idx = cbase + (long)m * N + n;
            float val = acc[i][j];
            if (MODE == 0) {
                C[idx] = val + bias[n];
            } else if (MODE == 1) {
                C[idx] += val;
            } else if (MODE == 2) {
                C[idx] = val * alpha;
            } else {
                float p = val + bias[n];
                float sg = 1.f / (1.f + expf(-p));
                C[idx] = sg * E1[idx] + (1.f - sg) * E2[idx];
            }
        }
    }
}

// ---------------- top-4 per row ----------------
__device__ __forceinline__ void ins4(float v, int id, float tv[4], int ti[4]) {
    if (v <= tv[3]) return;
    if (v > tv[0]) {
        tv[3]=tv[2]; ti[3]=ti[2]; tv[2]=tv[1]; ti[2]=ti[1];
        tv[1]=tv[0]; ti[1]=ti[0]; tv[0]=v; ti[0]=id;
    } else if (v > tv[1]) {
        tv[3]=tv[2]; ti[3]=ti[2]; tv[2]=tv[1]; ti[2]=ti[1];
        tv[1]=v; ti[1]=id;
    } else if (v > tv[2]) {
        tv[3]=tv[2]; ti[3]=ti[2]; tv[2]=v; ti[2]=id;
    } else {
        tv[3]=v; ti[3]=id;
    }
}

__global__ void __launch_bounds__(128)
topk_kernel(const float* __restrict__ logits, float* __restrict__ topv, int* __restrict__ topi)
{
    const int m = blockIdx.x;
    const float* p = logits + (long)m * Sdim;
    float tv[4] = {-1e30f, -1e30f, -1e30f, -1e30f};
    int   ti[4] = {-1, -1, -1, -1};
    for (int j = threadIdx.x; j < Sdim; j += 128) {
        ins4(p[j], j, tv, ti);
    }
    __shared__ float sv[128 * 4];
    __shared__ int   si[128 * 4];
#pragma unroll
    for (int j = 0; j < 4; j++) { sv[threadIdx.x * 4 + j] = tv[j]; si[threadIdx.x * 4 + j] = ti[j]; }
    __syncthreads();
    if (threadIdx.x == 0) {
        float rv[4] = {-1e30f, -1e30f, -1e30f, -1e30f};
        int   ri[4] = {-1, -1, -1, -1};
        for (int c = 0; c < 128 * 4; c++) ins4(sv[c], si[c], rv, ri);
#pragma unroll
        for (int j = 0; j < 4; j++) { topv[m * 4 + j] = rv[j]; topi[m * 4 + j] = ri[j]; }
    }
}

// ---------------- softmax + gather-weighted V ----------------
__global__ void __launch_bounds__(256)
route_kernel(const float* __restrict__ v, const float* __restrict__ topv,
             const int* __restrict__ topi, const float* __restrict__ temp,
             float* __restrict__ routed)
{
    const int m = blockIdx.x;
    const int b = m >> 12;              // m / 4096
    const float t = temp[0];
    float v0 = topv[m*4+0], v1 = topv[m*4+1], v2 = topv[m*4+2], v3 = topv[m*4+3];
    float mx = fmaxf(fmaxf(v0, v1), fmaxf(v2, v3));
    float e0 = expf((v0 - mx) / t), e1 = expf((v1 - mx) / t);
    float e2 = expf((v2 - mx) / t), e3 = expf((v3 - mx) / t);
    float inv = 1.f / (e0 + e1 + e2 + e3);
    e0 *= inv; e1 *= inv; e2 *= inv; e3 *= inv;

    const float* vb = v + (long)b * Sdim * Hdim;
    int i0 = topi[m*4+0], i1 = topi[m*4+1], i2 = topi[m*4+2], i3 = topi[m*4+3];
    const float4* r0 = reinterpret_cast<const float4*>(vb + (long)i0 * Hdim);
    const float4* r1 = reinterpret_cast<const float4*>(vb + (long)i1 * Hdim);
    const float4* r2 = reinterpret_cast<const float4*>(vb + (long)i2 * Hdim);
    const float4* r3 = reinterpret_cast<const float4*>(vb + (long)i3 * Hdim);

    int c = threadIdx.x;                // 256 threads x float4 = 1024 cols
    float4 a = r0[c], bb = r1[c], cc = r2[c], dd = r3[c];
    float4 o;
    o.x = e0*a.x + e1*bb.x + e2*cc.x + e3*dd.x;
    o.y = e0*a.y + e1*bb.y + e2*cc.y + e3*dd.y;
    o.z = e0*a.z + e1*bb.z + e2*cc.z + e3*dd.z;
    o.w = e0*a.w + e1*bb.w + e2*cc.w + e3*dd.w;
    reinterpret_cast<float4*>(routed + (long)m * Hdim)[c] = o;
}

// ---------------- LayerNorm (+ optional exact gelu) ----------------
template<int GELU>
__global__ void __launch_bounds__(256)
ln_kernel(const float* __restrict__ in, const float* __restrict__ g,
          const float* __restrict__ b, float* __restrict__ out)
{
    const int m = blockIdx.x;
    const int c = threadIdx.x;
    float4 x4 = reinterpret_cast<const float4*>(in + (long)m * Hdim)[c];
    float s  = x4.x + x4.y + x4.z + x4.w;
    float ss = x4.x*x4.x + x4.y*x4.y + x4.z*x4.z + x4.w*x4.w;
#pragma unroll
    for (int o = 16; o > 0; o >>= 1) {
        s  += __shfl_down_sync(0xffffffffu, s,  o);
        ss += __shfl_down_sync(0xffffffffu, ss, o);
    }
    __shared__ float red[2][8];
    int warp = c >> 5, lane = c & 31;
    if (lane == 0) { red[0][warp] = s; red[1][warp] = ss; }
    __syncthreads();
    if (c == 0) {
        float S_ = 0.f, SS_ = 0.f;
#pragma unroll
        for (int w = 0; w < 8; w++) { S_ += red[0][w]; SS_ += red[1][w]; }
        red[0][0] = S_; red[1][0] = SS_;
    }
    __syncthreads();
    float mu  = red[0][0] * (1.f / Hdim);
    float var = red[1][0] * (1.f / Hdim) - mu * mu;
    float rs  = rsqrtf(var + LNEPS);
    float4 g4 = reinterpret_cast<const float4*>(g)[c];
    float4 b4 = reinterpret_cast<const float4*>(b)[c];
    float4 y;
    y.x = (x4.x - mu) * rs * g4.x + b4.x;
    y.y = (x4.y - mu) * rs * g4.y + b4.y;
    y.z = (x4.z - mu) * rs * g4.z + b4.z;
    y.w = (x4.w - mu) * rs * g4.w + b4.w;
    if (GELU) {
        y.x = 0.5f * y.x * (1.f + erff(y.x * 0.70710678118f));
        y.y = 0.5f * y.y * (1.f + erff(y.y * 0.70710678118f));
        y.z = 0.5f * y.z * (1.f + erff(y.z * 0.70710678118f));
        y.w = 0.5f * y.w * (1.f + erff(y.w * 0.70710678118f));
    }
    reinterpret_cast<float4*>(out + (long)m * Hdim)[c] = y;
}

// ---------------- launch ----------------
extern "C" void kernel_launch(void* const* d_in, const int* in_sizes, int n_in,
                              void* d_out, int out_size)
{
    const float* x    = (const float*)d_in[0];
    const float* Wq   = (const float*)d_in[1];
    const float* bq   = (const float*)d_in[2];
    const float* Wk   = (const float*)d_in[3];
    const float* bk   = (const float*)d_in[4];
    const float* Wv   = (const float*)d_in[5];
    const float* bv   = (const float*)d_in[6];
    const float* Wc   = (const float*)d_in[7];
    const float* bc   = (const float*)d_in[8];
    const float* ln_g = (const float*)d_in[9];
    const float* ln_b = (const float*)d_in[10];
    const float* Wg1  = (const float*)d_in[11];
    const float* bg1  = (const float*)d_in[12];
    const float* gln_g= (const float*)d_in[13];
    const float* gln_b= (const float*)d_in[14];
    const float* Wg2  = (const float*)d_in[15];
    const float* bg2  = (const float*)d_in[16];
    const float* temp = (const float*)d_in[17];
    float* out = (float*)d_out;

    float *q_p, *k_p, *v_p, *logits_p, *topv_p, *routed_p, *cpre_p, *comb_p, *hpre_p, *h_p;
    int *topi_p;
    cudaGetSymbolAddress((void**)&q_p,      g_q);
    cudaGetSymbolAddress((void**)&k_p,      g_k);
    cudaGetSymbolAddress((void**)&v_p,      g_v);
    cudaGetSymbolAddress((void**)&logits_p, g_logits);
    cudaGetSymbolAddress((void**)&topv_p,   g_topv);
    cudaGetSymbolAddress((void**)&topi_p,   g_topi);
    cudaGetSymbolAddress((void**)&routed_p, g_routed);
    cudaGetSymbolAddress((void**)&cpre_p,   g_cpre);
    cudaGetSymbolAddress((void**)&comb_p,   g_combined);
    cudaGetSymbolAddress((void**)&hpre_p,   g_hpre);
    cudaGetSymbolAddress((void**)&h_p,      g_h);

    dim3 gNN(Hdim / BN, MTOT / BM, 1);      // (8, 64)
    dim3 gNT(Sdim / BN, Sdim / BM, Bdim);   // (32, 32, 2)

    // q, k, v
    sgemm128<0><<<gNN, 256>>>(x, Wq, bq, nullptr, nullptr, q_p, Hdim, Hdim, 0, 0, 0, 1.f);
    sgemm128<0><<<gNN, 256>>>(x, Wk, bk, nullptr, nullptr, k_p, Hdim, Hdim, 0, 0, 0, 1.f);
    sgemm128<0><<<gNN, 256>>>(x, Wv, bv, nullptr, nullptr, v_p, Hdim, Hdim, 0, 0, 0, 1.f);

    // logits = q @ k^T / 8  (per batch)
    sgemm128<2><<<gNT, 256>>>(q_p, k_p, nullptr, nullptr, nullptr, logits_p,
                              Hdim, Sdim,
                              (long)Sdim * Hdim, (long)Sdim * Hdim, (long)Sdim * Sdim,
                              INV_SCALE);

    // top-4 + softmax-routing gather
    topk_kernel<<<MTOT, 128>>>(logits_p, topv_p, topi_p);
    route_kernel<<<MTOT, 256>>>(v_p, topv_p, topi_p, temp, routed_p);

    // combined = LN(routed @ Wc + bc)
    sgemm128<0><<<gNN, 256>>>(routed_p, Wc, bc, nullptr, nullptr, cpre_p, Hdim, Hdim, 0, 0, 0, 1.f);
    ln_kernel<0><<<MTOT, 256>>>(cpre_p, ln_g, ln_b, comb_p);

    // hpre = x @ Wg1[:H] + bg1 + combined @ Wg1[H:]
    sgemm128<0><<<gNN, 256>>>(x,      Wg1,                bg1, nullptr, nullptr, hpre_p, Hdim, Hdim, 0, 0, 0, 1.f);
    sgemm128<1><<<gNN, 256>>>(comb_p, Wg1 + (long)Hdim * Hdim, nullptr, nullptr, nullptr, hpre_p, Hdim, Hdim, 0, 0, 0, 1.f);

    // h = gelu(LN(hpre))
    ln_kernel<1><<<MTOT, 256>>>(hpre_p, gln_g, gln_b, h_p);

    // out = sigmoid(h @ Wg2 + bg2) * combined + (1 - sigmoid) * x
    sgemm128<3><<<gNN, 256>>>(h_p, Wg2, bg2, comb_p, x, out, Hdim, Hdim, 0, 0, 0, 1.f);
}

// round 3
// speedup vs baseline: 1.9801x; 1.9801x over previous
#include <cuda_runtime.h>
#include <cuda_bf16.h>
#include <math.h>
#include <stdint.h>

#define Hdim 1024
#define Bdim 2
#define Sdim 4096
#define MTOT 8192
#define K3 3072
#define INV_SCALE 0.125f
#define LNEPS 1e-5f

// ---------------- scratch ----------------
__device__ __nv_bfloat16 g_xs[(long)MTOT*K3];
__device__ __nv_bfloat16 g_qs[(long)MTOT*K3];
__device__ __nv_bfloat16 g_ks[(long)MTOT*K3];
__device__ float g_v[(long)MTOT*Hdim];
__device__ float g_logits[(long)Bdim*Sdim*Sdim];
__device__ float g_topv[MTOT*4];
__device__ int   g_topi[MTOT*4];
__device__ __nv_bfloat16 g_rs[(long)MTOT*K3];
__device__ float g_cpre[(long)MTOT*Hdim];
__device__ float g_comb[(long)MTOT*Hdim];
__device__ __nv_bfloat16 g_cs[(long)MTOT*K3];
__device__ float g_hpre[(long)MTOT*Hdim];
__device__ __nv_bfloat16 g_hs[(long)MTOT*K3];
__device__ __nv_bfloat16 g_ws[7][(long)K3*Hdim];

// ---------------- mma helpers ----------------
__device__ __forceinline__ uint32_t s2u(const void* p){ return (uint32_t)__cvta_generic_to_shared(p); }

__device__ __forceinline__ void ldsm4(uint32_t& r0,uint32_t& r1,uint32_t& r2,uint32_t& r3, uint32_t a){
    asm volatile("ldmatrix.sync.aligned.m8n8.x4.shared.b16 {%0,%1,%2,%3},[%4];"
        :"=r"(r0),"=r"(r1),"=r"(r2),"=r"(r3):"r"(a));
}
__device__ __forceinline__ void ldsm4t(uint32_t& r0,uint32_t& r1,uint32_t& r2,uint32_t& r3, uint32_t a){
    asm volatile("ldmatrix.sync.aligned.m8n8.x4.trans.shared.b16 {%0,%1,%2,%3},[%4];"
        :"=r"(r0),"=r"(r1),"=r"(r2),"=r"(r3):"r"(a));
}
__device__ __forceinline__ void mma16816(float* c, const uint32_t* a, const uint32_t* b){
    asm volatile("mma.sync.aligned.m16n8k16.row.col.f32.bf16.bf16.f32 "
        "{%0,%1,%2,%3},{%4,%5,%6,%7},{%8,%9},{%0,%1,%2,%3};"
        : "+f"(c[0]),"+f"(c[1]),"+f"(c[2]),"+f"(c[3])
        : "r"(a[0]),"r"(a[1]),"r"(a[2]),"r"(a[3]),"r"(b[0]),"r"(b[1]));
}

__device__ __forceinline__ void split2(float v, __nv_bfloat16& h, __nv_bfloat16& l){
    h = __float2bfloat16(v);
    l = __float2bfloat16(v - __bfloat162float(h));
}

// ---------------- bf16 tensor-core GEMM ----------------
// BM=128, BN=128, BK=32, 256 threads (8 warps: 2x4), warp tile 64x32.
// TRANSB=false: B is [K,N] row-major.  TRANSB=true: B is [N,K] row-major (NT).
// MODE 0: fp32 C = acc + bias[n]
// MODE 1: fp32 C += acc
// MODE 2: fp32 C = acc * alpha
// MODE 3: sg = sigmoid(acc+bias); C = sg*E1 + (1-sg)*E2
// MODE 5: bf16 split A-layout  [hi | lo | hi] rows of K3
// MODE 6: bf16 split B-layout  [hi | hi | lo] rows of K3
#define BMt 128
#define BNt 128
#define BKt 32
#define ASTR 40      // 32+8 elems: conflict-free ldmatrix
#define BSTRNN 136   // 128+8 elems

template<bool TRANSB, int MODE>
__global__ void __launch_bounds__(256)
mma_gemm(const __nv_bfloat16* __restrict__ A, const __nv_bfloat16* __restrict__ B,
         const float* __restrict__ bias, const float* __restrict__ E1,
         const float* __restrict__ E2, void* __restrict__ Cptr,
         int K, int N, long sA, long sB, long sC, float alpha)
{
    constexpr int BSN = TRANSB ? (BNt*ASTR) : (BKt*BSTRNN);
    __shared__ __nv_bfloat16 As[2][BMt*ASTR];
    __shared__ __nv_bfloat16 Bs[2][BSN];

    const int tid  = threadIdx.x;
    const int lane = tid & 31;
    const int warp = tid >> 5;
    const int wm = warp & 1;
    const int wn = warp >> 1;
    const int m0 = blockIdx.y * BMt;
    const int n0 = blockIdx.x * BNt;

    const __nv_bfloat16* Ab = A + blockIdx.z*sA + (long)m0*K;
    const __nv_bfloat16* Bb = TRANSB ? (B + blockIdx.z*sB + (long)n0*K) : (B + n0);

    float acc[4][4][4];
#pragma unroll
    for (int i=0;i<4;i++)
#pragma unroll
        for (int j=0;j<4;j++)
#pragma unroll
            for (int h=0;h<4;h++) acc[i][j][h] = 0.f;

    uint2 ra[4];
    uint2 rbt[4];
    uint4 rbn[2];

    auto loadA = [&](int k0){
#pragma unroll
        for (int l=0;l<4;l++){
            int id = tid + l*256; int r = id>>3; int c = (id&7)*4;
            ra[l] = *reinterpret_cast<const uint2*>(Ab + (long)r*K + k0 + c);
        }
    };
    auto storeA = [&](int buf){
#pragma unroll
        for (int l=0;l<4;l++){
            int id = tid + l*256; int r = id>>3; int c = (id&7)*4;
            *reinterpret_cast<uint2*>(&As[buf][r*ASTR + c]) = ra[l];
        }
    };
    auto loadB = [&](int k0){
        if (TRANSB){
#pragma unroll
            for (int l=0;l<4;l++){
                int id = tid + l*256; int r = id>>3; int c = (id&7)*4;
                rbt[l] = *reinterpret_cast<const uint2*>(Bb + (long)r*K + k0 + c);
            }
        } else {
#pragma unroll
            for (int l=0;l<2;l++){
                int id = tid + l*256; int r = id>>4; int c = (id&15)*8;
                rbn[l] = *reinterpret_cast<const uint4*>(Bb + (long)(k0+r)*N + c);
            }
        }
    };
    auto storeB = [&](int buf){
        if (TRANSB){
#pragma unroll
            for (int l=0;l<4;l++){
                int id = tid + l*256; int r = id>>3; int c = (id&7)*4;
                *reinterpret_cast<uint2*>(&Bs[buf][r*ASTR + c]) = rbt[l];
            }
        } else {
#pragma unroll
            for (int l=0;l<2;l++){
                int id = tid + l*256; int r = id>>4; int c = (id&15)*8;
                *reinterpret_cast<uint4*>(&Bs[buf][r*BSTRNN + c]) = rbn[l];
            }
        }
    };

    const int nt = K / BKt;
    loadA(0); storeA(0);
    loadB(0); storeB(0);
    __syncthreads();
    int buf = 0;

    for (int t = 0; t < nt; t++){
        if (t+1 < nt){ loadA((t+1)*BKt); loadB((t+1)*BKt); }
#pragma unroll
        for (int ks=0; ks<2; ks++){
            uint32_t af[4][4];
#pragma unroll
            for (int mi=0; mi<4; mi++){
                int row = wm*64 + mi*16 + (lane&15);
                int col = ks*16 + ((lane>>4)<<3);
                ldsm4(af[mi][0],af[mi][1],af[mi][2],af[mi][3],
                      s2u(&As[buf][row*ASTR + col]));
            }
            uint32_t bf[4][2];
            if (TRANSB){
#pragma unroll
                for (int nj=0; nj<2; nj++){
                    int g = lane>>3;
                    int row = wn*32 + nj*16 + ((g>>1)<<3) + (lane&7);
                    int col = ks*16 + ((g&1)<<3);
                    uint32_t r0,r1,r2,r3;
                    ldsm4(r0,r1,r2,r3, s2u(&Bs[buf][row*ASTR + col]));
                    bf[nj*2][0]=r0; bf[nj*2][1]=r1; bf[nj*2+1][0]=r2; bf[nj*2+1][1]=r3;
                }
            } else {
#pragma unroll
                for (int nj=0; nj<2; nj++){
                    int row = ks*16 + (lane&15);
                    int col = wn*32 + nj*16 + ((lane>>4)<<3);
                    uint32_t r0,r1,r2,r3;
                    ldsm4t(r0,r1,r2,r3, s2u(&Bs[buf][row*BSTRNN + col]));
                    bf[nj*2][0]=r0; bf[nj*2][1]=r1; bf[nj*2+1][0]=r2; bf[nj*2+1][1]=r3;
                }
            }
#pragma unroll
            for (int mi=0;mi<4;mi++)
#pragma unroll
                for (int ni=0;ni<4;ni++)
                    mma16816(acc[mi][ni], af[mi], bf[ni]);
        }
        if (t+1 < nt){ storeA(buf^1); storeB(buf^1); }
        __syncthreads();
        buf ^= 1;
    }

    const long cb = blockIdx.z*sC;
#pragma unroll
    for (int mi=0;mi<4;mi++){
#pragma unroll
        for (int ni=0;ni<4;ni++){
#pragma unroll
            for (int h=0; h<2; h++){
                int row = m0 + wm*64 + mi*16 + (lane>>2) + h*8;
                int col = n0 + wn*32 + ni*8 + (lane&3)*2;
                float v0 = acc[mi][ni][h*2], v1 = acc[mi][ni][h*2+1];
                if (MODE == 0){
                    long idx = cb + (long)row*N + col;
                    float* C = (float*)Cptr;
                    C[idx]   = v0 + bias[col];
                    C[idx+1] = v1 + bias[col+1];
                } else if (MODE == 1){
                    long idx = cb + (long)row*N + col;
                    float* C = (float*)Cptr;
                    C[idx]   += v0;
                    C[idx+1] += v1;
                } else if (MODE == 2){
                    long idx = cb + (long)row*N + col;
                    float2 o; o.x = v0*alpha; o.y = v1*alpha;
                    *reinterpret_cast<float2*>((float*)Cptr + idx) = o;
                } else if (MODE == 3){
                    long idx = cb + (long)row*N + col;
                    float* C = (float*)Cptr;
                    float p0 = v0 + bias[col],   p1 = v1 + bias[col+1];
                    float s0 = 1.f/(1.f+expf(-p0)), s1 = 1.f/(1.f+expf(-p1));
                    C[idx]   = s0*E1[idx]   + (1.f-s0)*E2[idx];
                    C[idx+1] = s1*E1[idx+1] + (1.f-s1)*E2[idx+1];
                } else {
                    // split outputs into K3 layout
                    __nv_bfloat16* C = (__nv_bfloat16*)Cptr;
                    long base = (long)row*K3 + col;
                    float p0 = v0 + bias[col], p1 = v1 + bias[col+1];
                    __nv_bfloat16 h0,l0,h1,l1;
                    split2(p0,h0,l0); split2(p1,h1,l1);
                    if (MODE == 5){       // A-layout: hi | lo | hi
                        C[base]        = h0; C[base+1]        = h1;
                        C[base+1024]   = l0; C[base+1025]     = l1;
                        C[base+2048]   = h0; C[base+2049]     = h1;
                    } else {              // MODE 6, B-layout: hi | hi | lo
                        C[base]        = h0; C[base+1]        = h1;
                        C[base+1024]   = h0; C[base+1025]     = h1;
                        C[base+2048]   = l0; C[base+2049]     = l1;
                    }
                }
            }
        }
    }
}

// ---------------- split kernels ----------------
__global__ void __launch_bounds__(256)
split_x_kernel(const float* __restrict__ in, __nv_bfloat16* __restrict__ out)
{
    long i = (long)blockIdx.x*256 + threadIdx.x;
    int m = (int)(i >> 10), k = (int)(i & 1023);
    float v = in[i];
    __nv_bfloat16 h,l; split2(v,h,l);
    long ob = (long)m*K3 + k;
    out[ob] = h; out[ob+1024] = l; out[ob+2048] = h;
}

struct WPtrs { const float* in[7]; __nv_bfloat16* out[7]; };
__global__ void __launch_bounds__(256)
split_w_kernel(WPtrs p)
{
    int w = blockIdx.z;
    long i = (long)blockIdx.x*256 + threadIdx.x;
    float v = p.in[w][i];
    __nv_bfloat16 h,l; split2(v,h,l);
    p.out[w][i] = h;
    p.out[w][i + (long)1024*1024] = h;
    p.out[w][i + (long)2*1024*1024] = l;
}

// ---------------- top-4 per row ----------------
__device__ __forceinline__ void ins4(float v, int id, float tv[4], int ti[4]) {
    if (v <= tv[3]) return;
    if (v > tv[0]) { tv[3]=tv[2]; ti[3]=ti[2]; tv[2]=tv[1]; ti[2]=ti[1];
                     tv[1]=tv[0]; ti[1]=ti[0]; tv[0]=v; ti[0]=id; }
    else if (v > tv[1]) { tv[3]=tv[2]; ti[3]=ti[2]; tv[2]=tv[1]; ti[2]=ti[1]; tv[1]=v; ti[1]=id; }
    else if (v > tv[2]) { tv[3]=tv[2]; ti[3]=ti[2]; tv[2]=v; ti[2]=id; }
    else { tv[3]=v; ti[3]=id; }
}

__global__ void __launch_bounds__(128)
topk_kernel(const float* __restrict__ logits, float* __restrict__ topv, int* __restrict__ topi)
{
    const int m = blockIdx.x;
    const float* p = logits + (long)m * Sdim;
    float tv[4] = {-1e30f,-1e30f,-1e30f,-1e30f};
    int   ti[4] = {-1,-1,-1,-1};
    for (int j = threadIdx.x; j < Sdim; j += 128) ins4(p[j], j, tv, ti);
    __shared__ float sv[128*4];
    __shared__ int   si[128*4];
#pragma unroll
    for (int j=0;j<4;j++){ sv[threadIdx.x*4+j]=tv[j]; si[threadIdx.x*4+j]=ti[j]; }
    __syncthreads();
    if (threadIdx.x == 0){
        float rv[4] = {-1e30f,-1e30f,-1e30f,-1e30f};
        int   ri[4] = {-1,-1,-1,-1};
        for (int c=0;c<128*4;c++) ins4(sv[c], si[c], rv, ri);
#pragma unroll
        for (int j=0;j<4;j++){ topv[m*4+j]=rv[j]; topi[m*4+j]=ri[j]; }
    }
}

// ---------------- softmax + gather-weighted V -> split bf16 ----------------
__global__ void __launch_bounds__(256)
route_kernel(const float* __restrict__ v, const float* __restrict__ topv,
             const int* __restrict__ topi, const float* __restrict__ temp,
             __nv_bfloat16* __restrict__ rs)
{
    const int m = blockIdx.x;
    const int b = m >> 12;
    const float t = temp[0];
    float v0 = topv[m*4+0], v1 = topv[m*4+1], v2 = topv[m*4+2], v3 = topv[m*4+3];
    float mx = fmaxf(fmaxf(v0,v1), fmaxf(v2,v3));
    float e0 = expf((v0-mx)/t), e1 = expf((v1-mx)/t);
    float e2 = expf((v2-mx)/t), e3 = expf((v3-mx)/t);
    float inv = 1.f/(e0+e1+e2+e3);
    e0*=inv; e1*=inv; e2*=inv; e3*=inv;

    const float* vb = v + (long)b*Sdim*Hdim;
    int i0=topi[m*4+0], i1=topi[m*4+1], i2=topi[m*4+2], i3=topi[m*4+3];
    const float4* r0 = reinterpret_cast<const float4*>(vb + (long)i0*Hdim);
    const float4* r1 = reinterpret_cast<const float4*>(vb + (long)i1*Hdim);
    const float4* r2 = reinterpret_cast<const float4*>(vb + (long)i2*Hdim);
    const float4* r3 = reinterpret_cast<const float4*>(vb + (long)i3*Hdim);

    int c = threadIdx.x;
    float4 a = r0[c], bb = r1[c], cc = r2[c], dd = r3[c];
    float o[4];
    o[0] = e0*a.x + e1*bb.x + e2*cc.x + e3*dd.x;
    o[1] = e0*a.y + e1*bb.y + e2*cc.y + e3*dd.y;
    o[2] = e0*a.z + e1*bb.z + e2*cc.z + e3*dd.z;
    o[3] = e0*a.w + e1*bb.w + e2*cc.w + e3*dd.w;
    long ob = (long)m*K3 + c*4;
#pragma unroll
    for (int j=0;j<4;j++){
        __nv_bfloat16 h,l; split2(o[j],h,l);
        rs[ob+j] = h; rs[ob+1024+j] = l; rs[ob+2048+j] = h;
    }
}

// ---------------- LayerNorm (+gelu) -> optional fp32 + split bf16 ----------------
template<int GELU>
__global__ void __launch_bounds__(256)
ln_kernel(const float* __restrict__ in, const float* __restrict__ g,
          const float* __restrict__ b, float* __restrict__ outf,
          __nv_bfloat16* __restrict__ outs)
{
    const int m = blockIdx.x;
    const int c = threadIdx.x;
    float4 x4 = reinterpret_cast<const float4*>(in + (long)m*Hdim)[c];
    float s  = x4.x + x4.y + x4.z + x4.w;
    float ss = x4.x*x4.x + x4.y*x4.y + x4.z*x4.z + x4.w*x4.w;
#pragma unroll
    for (int o=16;o>0;o>>=1){
        s  += __shfl_down_sync(0xffffffffu, s,  o);
        ss += __shfl_down_sync(0xffffffffu, ss, o);
    }
    __shared__ float red[2][8];
    int warp = c>>5, lane = c&31;
    if (lane==0){ red[0][warp]=s; red[1][warp]=ss; }
    __syncthreads();
    if (c==0){
        float S_=0.f, SS_=0.f;
#pragma unroll
        for (int w=0;w<8;w++){ S_+=red[0][w]; SS_+=red[1][w]; }
        red[0][0]=S_; red[1][0]=SS_;
    }
    __syncthreads();
    float mu  = red[0][0]*(1.f/Hdim);
    float var = red[1][0]*(1.f/Hdim) - mu*mu;
    float rs  = rsqrtf(var + LNEPS);
    float4 g4 = reinterpret_cast<const float4*>(g)[c];
    float4 b4 = reinterpret_cast<const float4*>(b)[c];
    float y[4];
    y[0] = (x4.x-mu)*rs*g4.x + b4.x;
    y[1] = (x4.y-mu)*rs*g4.y + b4.y;
    y[2] = (x4.z-mu)*rs*g4.z + b4.z;
    y[3] = (x4.w-mu)*rs*g4.w + b4.w;
    if (GELU){
#pragma unroll
        for (int j=0;j<4;j++) y[j] = 0.5f*y[j]*(1.f + erff(y[j]*0.70710678118f));
    }
    if (outf){
        float4 yo; yo.x=y[0]; yo.y=y[1]; yo.z=y[2]; yo.w=y[3];
        reinterpret_cast<float4*>(outf + (long)m*Hdim)[c] = yo;
    }
    long ob = (long)m*K3 + c*4;
#pragma unroll
    for (int j=0;j<4;j++){
        __nv_bfloat16 h,l; split2(y[j],h,l);
        outs[ob+j] = h; outs[ob+1024+j] = l; outs[ob+2048+j] = h;
    }
}

// ---------------- launch ----------------
extern "C" void kernel_launch(void* const* d_in, const int* in_sizes, int n_in,
                              void* d_out, int out_size)
{
    const float* x    = (const float*)d_in[0];
    const float* Wq   = (const float*)d_in[1];
    const float* bq   = (const float*)d_in[2];
    const float* Wk   = (const float*)d_in[3];
    const float* bk   = (const float*)d_in[4];
    const float* Wv   = (const float*)d_in[5];
    const float* bv   = (const float*)d_in[6];
    const float* Wc   = (const float*)d_in[7];
    const float* bc   = (const float*)d_in[8];
    const float* ln_g = (const float*)d_in[9];
    const float* ln_b = (const float*)d_in[10];
    const float* Wg1  = (const float*)d_in[11];
    const float* bg1  = (const float*)d_in[12];
    const float* gln_g= (const float*)d_in[13];
    const float* gln_b= (const float*)d_in[14];
    const float* Wg2  = (const float*)d_in[15];
    const float* bg2  = (const float*)d_in[16];
    const float* temp = (const float*)d_in[17];
    float* out = (float*)d_out;

    __nv_bfloat16 *xs_p, *qs_p, *ks_p, *rs_p, *cs_p, *hs_p, *ws_p;
    float *v_p, *logits_p, *topv_p, *cpre_p, *comb_p, *hpre_p;
    int *topi_p;
    cudaGetSymbolAddress((void**)&xs_p,    g_xs);
    cudaGetSymbolAddress((void**)&qs_p,    g_qs);
    cudaGetSymbolAddress((void**)&ks_p,    g_ks);
    cudaGetSymbolAddress((void**)&v_p,     g_v);
    cudaGetSymbolAddress((void**)&logits_p,g_logits);
    cudaGetSymbolAddress((void**)&topv_p,  g_topv);
    cudaGetSymbolAddress((void**)&topi_p,  g_topi);
    cudaGetSymbolAddress((void**)&rs_p,    g_rs);
    cudaGetSymbolAddress((void**)&cpre_p,  g_cpre);
    cudaGetSymbolAddress((void**)&comb_p,  g_comb);
    cudaGetSymbolAddress((void**)&cs_p,    g_cs);
    cudaGetSymbolAddress((void**)&hpre_p,  g_hpre);
    cudaGetSymbolAddress((void**)&hs_p,    g_hs);
    cudaGetSymbolAddress((void**)&ws_p,    g_ws);

    const long WSZ = (long)K3*Hdim;
    __nv_bfloat16 *wq_p = ws_p,       *wk_p = ws_p + WSZ,   *wv_p = ws_p + 2*WSZ,
                  *wc_p = ws_p+3*WSZ, *wg1a_p = ws_p+4*WSZ, *wg1b_p = ws_p+5*WSZ,
                  *wg2_p = ws_p+6*WSZ;

    split_x_kernel<<<MTOT*Hdim/256, 256>>>(x, xs_p);
    WPtrs wp;
    wp.in[0]=Wq; wp.in[1]=Wk; wp.in[2]=Wv; wp.in[3]=Wc;
    wp.in[4]=Wg1; wp.in[5]=Wg1 + (long)Hdim*Hdim; wp.in[6]=Wg2;
    wp.out[0]=wq_p; wp.out[1]=wk_p; wp.out[2]=wv_p; wp.out[3]=wc_p;
    wp.out[4]=wg1a_p; wp.out[5]=wg1b_p; wp.out[6]=wg2_p;
    split_w_kernel<<<dim3(Hdim*Hdim/256,1,7), 256>>>(wp);

    dim3 gNN(Hdim/BNt, MTOT/BMt, 1);       // (8, 64)
    dim3 gNT(Sdim/BNt, Sdim/BMt, Bdim);    // (32, 32, 2)

    // q (A-split out), k (B-split out), v (fp32 out)
    mma_gemm<false,5><<<gNN,256>>>(xs_p, wq_p, bq, nullptr, nullptr, qs_p, K3, Hdim, 0,0,0, 1.f);
    mma_gemm<false,6><<<gNN,256>>>(xs_p, wk_p, bk, nullptr, nullptr, ks_p, K3, Hdim, 0,0,0, 1.f);
    mma_gemm<false,0><<<gNN,256>>>(xs_p, wv_p, bv, nullptr, nullptr, v_p,  K3, Hdim, 0,0,0, 1.f);

    // logits = q @ k^T / 8  (bf16x3, NT, K=3072)
    mma_gemm<true,2><<<gNT,256>>>(qs_p, ks_p, nullptr, nullptr, nullptr, logits_p,
                                  K3, Sdim, (long)Sdim*K3, (long)Sdim*K3,
                                  (long)Sdim*Sdim, INV_SCALE);

    topk_kernel<<<MTOT,128>>>(logits_p, topv_p, topi_p);
    route_kernel<<<MTOT,256>>>(v_p, topv_p, topi_p, temp, rs_p);

    // combined = LN(routed @ Wc + bc)
    mma_gemm<false,0><<<gNN,256>>>(rs_p, wc_p, bc, nullptr, nullptr, cpre_p, K3, Hdim, 0,0,0, 1.f);
    ln_kernel<0><<<MTOT,256>>>(cpre_p, ln_g, ln_b, comb_p, cs_p);

    // hpre = x @ Wg1a + bg1 + combined @ Wg1b
    mma_gemm<false,0><<<gNN,256>>>(xs_p, wg1a_p, bg1, nullptr, nullptr, hpre_p, K3, Hdim, 0,0,0, 1.f);
    mma_gemm<false,1><<<gNN,256>>>(cs_p, wg1b_p, nullptr, nullptr, nullptr, hpre_p, K3, Hdim, 0,0,0, 1.f);

    // h = gelu(LN(hpre))
    ln_kernel<1><<<MTOT,256>>>(hpre_p, gln_g, gln_b, nullptr, hs_p);

    // out = sigmoid(h @ Wg2 + bg2) * combined + (1-s) * x
    mma_gemm<false,3><<<gNN,256>>>(hs_p, wg2_p, bg2, comb_p, x, out, K3, Hdim, 0,0,0, 1.f);
}

// round 4
// speedup vs baseline: 2.2127x; 1.1174x over previous
#include <cuda_runtime.h>
#include <cuda_bf16.h>
#include <math.h>
#include <stdint.h>

#define Hdim 1024
#define Bdim 2
#define Sdim 4096
#define MTOT 8192
#define K3 3072
#define INV_SCALE 0.125f
#define LNEPS 1e-5f

// ---------------- scratch ----------------
__device__ __nv_bfloat16 g_xs[(long)MTOT*K3];
__device__ __nv_bfloat16 g_qs[(long)MTOT*K3];
__device__ __nv_bfloat16 g_ks[(long)MTOT*K3];
__device__ float g_v[(long)MTOT*Hdim];
__device__ float g_logits[(long)Bdim*Sdim*Sdim];
__device__ float g_topv[MTOT*4];
__device__ int   g_topi[MTOT*4];
__device__ __nv_bfloat16 g_rs[(long)MTOT*K3];
__device__ float g_cpre[(long)MTOT*Hdim];
__device__ float g_comb[(long)MTOT*Hdim];
__device__ __nv_bfloat16 g_cs[(long)MTOT*K3];
__device__ float g_hpre[(long)MTOT*Hdim];
__device__ __nv_bfloat16 g_hs[(long)MTOT*K3];
__device__ __nv_bfloat16 g_ws[7][(long)K3*Hdim];

// ---------------- helpers ----------------
__device__ __forceinline__ uint32_t s2u(const void* p){ return (uint32_t)__cvta_generic_to_shared(p); }

__device__ __forceinline__ void ldsm4(uint32_t& r0,uint32_t& r1,uint32_t& r2,uint32_t& r3, uint32_t a){
    asm volatile("ldmatrix.sync.aligned.m8n8.x4.shared.b16 {%0,%1,%2,%3},[%4];"
        :"=r"(r0),"=r"(r1),"=r"(r2),"=r"(r3):"r"(a));
}
__device__ __forceinline__ void ldsm4t(uint32_t& r0,uint32_t& r1,uint32_t& r2,uint32_t& r3, uint32_t a){
    asm volatile("ldmatrix.sync.aligned.m8n8.x4.trans.shared.b16 {%0,%1,%2,%3},[%4];"
        :"=r"(r0),"=r"(r1),"=r"(r2),"=r"(r3):"r"(a));
}
__device__ __forceinline__ void mma16816(float* c, const uint32_t* a, const uint32_t* b){
    asm volatile("mma.sync.aligned.m16n8k16.row.col.f32.bf16.bf16.f32 "
        "{%0,%1,%2,%3},{%4,%5,%6,%7},{%8,%9},{%0,%1,%2,%3};"
        : "+f"(c[0]),"+f"(c[1]),"+f"(c[2]),"+f"(c[3])
        : "r"(a[0]),"r"(a[1]),"r"(a[2]),"r"(a[3]),"r"(b[0]),"r"(b[1]));
}
__device__ __forceinline__ void cpa16(uint32_t dst, const void* src){
    asm volatile("cp.async.cg.shared.global [%0], [%1], 16;" :: "r"(dst), "l"(src));
}
__device__ __forceinline__ void cpa_commit(){ asm volatile("cp.async.commit_group;"); }
template<int N> __device__ __forceinline__ void cpa_wait(){ asm volatile("cp.async.wait_group %0;"::"n"(N)); }

__device__ __forceinline__ void split2(float v, __nv_bfloat16& h, __nv_bfloat16& l){
    h = __float2bfloat16(v);
    l = __float2bfloat16(v - __bfloat162float(h));
}

// ---------------- bf16 tensor-core GEMM, 4-stage cp.async pipeline ----------------
// BM=128, BN=128, BK=32, 256 threads (8 warps: 2x4), warp tile 64x32.
// TRANSB=false: B is [K,N] row-major.  TRANSB=true: B is [N,K] row-major (NT).
// MODE 0: fp32 C = acc + bias[n]
// MODE 1: fp32 C += acc
// MODE 2: fp32 C = acc * alpha
// MODE 3: sg = sigmoid(acc+bias); C = sg*E1 + (1-sg)*E2
// MODE 5: bf16 split A-layout  [hi | lo | hi] rows of K3
// MODE 6: bf16 split B-layout  [hi | hi | lo] rows of K3
#define BMt 128
#define BNt 128
#define BKt 32
#define ASTR 40      // 32+8 elems: conflict-free ldmatrix; 80B row (16B-aligned)
#define BSTRNN 136   // 128+8 elems: 272B row (16B-aligned)
#define NSTAGE 4

template<bool TRANSB, int MODE>
__global__ void __launch_bounds__(256)
mma_gemm(const __nv_bfloat16* __restrict__ A, const __nv_bfloat16* __restrict__ B,
         const float* __restrict__ bias, const float* __restrict__ E1,
         const float* __restrict__ E2, void* __restrict__ Cptr,
         int K, int N, long sA, long sB, long sC, float alpha)
{
    constexpr int ASTAGE = BMt*ASTR*2;                          // bytes
    constexpr int BSTAGE = TRANSB ? (BNt*ASTR*2) : (BKt*BSTRNN*2);
    extern __shared__ char sm[];
    const uint32_t aBase = s2u(sm);
    const uint32_t bBase = aBase + NSTAGE*ASTAGE;

    const int tid  = threadIdx.x;
    const int lane = tid & 31;
    const int warp = tid >> 5;
    const int wm = warp & 1;
    const int wn = warp >> 1;
    const int m0 = blockIdx.y * BMt;
    const int n0 = blockIdx.x * BNt;

    const __nv_bfloat16* Ab = A + blockIdx.z*sA + (long)m0*K;
    const __nv_bfloat16* Bb = TRANSB ? (B + blockIdx.z*sB + (long)n0*K) : (B + n0);

    float acc[4][4][4];
#pragma unroll
    for (int i=0;i<4;i++)
#pragma unroll
        for (int j=0;j<4;j++)
#pragma unroll
            for (int h=0;h<4;h++) acc[i][j][h] = 0.f;

    auto copyA = [&](int st, int k0){
        uint32_t base = aBase + st*ASTAGE;
#pragma unroll
        for (int l=0;l<2;l++){
            int id = tid + l*256; int r = id>>2; int c = (id&3)*8;
            cpa16(base + (r*ASTR + c)*2, Ab + (long)r*K + k0 + c);
        }
    };
    auto copyB = [&](int st, int k0){
        uint32_t base = bBase + st*BSTAGE;
        if (TRANSB){
#pragma unroll
            for (int l=0;l<2;l++){
                int id = tid + l*256; int r = id>>2; int c = (id&3)*8;
                cpa16(base + (r*ASTR + c)*2, Bb + (long)r*K + k0 + c);
            }
        } else {
#pragma unroll
            for (int l=0;l<2;l++){
                int id = tid + l*256; int r = id>>4; int c = (id&15)*8;
                cpa16(base + (r*BSTRNN + c)*2, Bb + (long)(k0+r)*N + c);
            }
        }
    };

    const int nt = K / BKt;
#pragma unroll
    for (int s=0; s<NSTAGE-1; s++){
        copyA(s, s*BKt); copyB(s, s*BKt); cpa_commit();
    }

    int buf = 0;
    for (int t = 0; t < nt; t++){
        cpa_wait<NSTAGE-2>();
        __syncthreads();
        const uint32_t aS = aBase + buf*ASTAGE;
        const uint32_t bS = bBase + buf*BSTAGE;
#pragma unroll
        for (int ks=0; ks<2; ks++){
            uint32_t af[4][4];
#pragma unroll
            for (int mi=0; mi<4; mi++){
                int row = wm*64 + mi*16 + (lane&15);
                int col = ks*16 + ((lane>>4)<<3);
                ldsm4(af[mi][0],af[mi][1],af[mi][2],af[mi][3],
                      aS + (row*ASTR + col)*2);
            }
            uint32_t bf[4][2];
            if (TRANSB){
#pragma unroll
                for (int nj=0; nj<2; nj++){
                    int g = lane>>3;
                    int row = wn*32 + nj*16 + ((g>>1)<<3) + (lane&7);
                    int col = ks*16 + ((g&1)<<3);
                    uint32_t r0,r1,r2,r3;
                    ldsm4(r0,r1,r2,r3, bS + (row*ASTR + col)*2);
                    bf[nj*2][0]=r0; bf[nj*2][1]=r1; bf[nj*2+1][0]=r2; bf[nj*2+1][1]=r3;
                }
            } else {
#pragma unroll
                for (int nj=0; nj<2; nj++){
                    int row = ks*16 + (lane&15);
                    int col = wn*32 + nj*16 + ((lane>>4)<<3);
                    uint32_t r0,r1,r2,r3;
                    ldsm4t(r0,r1,r2,r3, bS + (row*BSTRNN + col)*2);
                    bf[nj*2][0]=r0; bf[nj*2][1]=r1; bf[nj*2+1][0]=r2; bf[nj*2+1][1]=r3;
                }
            }
#pragma unroll
            for (int mi=0;mi<4;mi++)
#pragma unroll
                for (int ni=0;ni<4;ni++)
                    mma16816(acc[mi][ni], af[mi], bf[ni]);
        }
        int tn = t + NSTAGE-1;
        if (tn < nt){
            int st = buf + NSTAGE-1; if (st >= NSTAGE) st -= NSTAGE;
            copyA(st, tn*BKt); copyB(st, tn*BKt);
        }
        cpa_commit();
        buf = (buf+1 == NSTAGE) ? 0 : buf+1;
    }

    const long cb = blockIdx.z*sC;
#pragma unroll
    for (int mi=0;mi<4;mi++){
#pragma unroll
        for (int ni=0;ni<4;ni++){
#pragma unroll
            for (int h=0; h<2; h++){
                int row = m0 + wm*64 + mi*16 + (lane>>2) + h*8;
                int col = n0 + wn*32 + ni*8 + (lane&3)*2;
                float v0 = acc[mi][ni][h*2], v1 = acc[mi][ni][h*2+1];
                if (MODE == 0){
                    long idx = cb + (long)row*N + col;
                    float* C = (float*)Cptr;
                    C[idx]   = v0 + bias[col];
                    C[idx+1] = v1 + bias[col+1];
                } else if (MODE == 1){
                    long idx = cb + (long)row*N + col;
                    float* C = (float*)Cptr;
                    C[idx]   += v0;
                    C[idx+1] += v1;
                } else if (MODE == 2){
                    long idx = cb + (long)row*N + col;
                    float2 o; o.x = v0*alpha; o.y = v1*alpha;
                    *reinterpret_cast<float2*>((float*)Cptr + idx) = o;
                } else if (MODE == 3){
                    long idx = cb + (long)row*N + col;
                    float* C = (float*)Cptr;
                    float p0 = v0 + bias[col],   p1 = v1 + bias[col+1];
                    float s0 = 1.f/(1.f+expf(-p0)), s1 = 1.f/(1.f+expf(-p1));
                    C[idx]   = s0*E1[idx]   + (1.f-s0)*E2[idx];
                    C[idx+1] = s1*E1[idx+1] + (1.f-s1)*E2[idx+1];
                } else {
                    __nv_bfloat16* C = (__nv_bfloat16*)Cptr;
                    long base = (long)row*K3 + col;
                    float p0 = v0 + bias[col], p1 = v1 + bias[col+1];
                    __nv_bfloat16 h0,l0,h1,l1;
                    split2(p0,h0,l0); split2(p1,h1,l1);
                    if (MODE == 5){       // A-layout: hi | lo | hi
                        C[base]      = h0; C[base+1]    = h1;
                        C[base+1024] = l0; C[base+1025] = l1;
                        C[base+2048] = h0; C[base+2049] = h1;
                    } else {              // MODE 6, B-layout: hi | hi | lo
                        C[base]      = h0; C[base+1]    = h1;
                        C[base+1024] = h0; C[base+1025] = h1;
                        C[base+2048] = l0; C[base+2049] = l1;
                    }
                }
            }
        }
    }
}

// ---------------- split kernels ----------------
__global__ void __launch_bounds__(256)
split_x_kernel(const float* __restrict__ in, __nv_bfloat16* __restrict__ out)
{
    long i = (long)blockIdx.x*256 + threadIdx.x;
    int m = (int)(i >> 10), k = (int)(i & 1023);
    float v = in[i];
    __nv_bfloat16 h,l; split2(v,h,l);
    long ob = (long)m*K3 + k;
    out[ob] = h; out[ob+1024] = l; out[ob+2048] = h;
}

struct WPtrs { const float* in[7]; __nv_bfloat16* out[7]; };
__global__ void __launch_bounds__(256)
split_w_kernel(WPtrs p)
{
    int w = blockIdx.z;
    long i = (long)blockIdx.x*256 + threadIdx.x;
    float v = p.in[w][i];
    __nv_bfloat16 h,l; split2(v,h,l);
    p.out[w][i] = h;
    p.out[w][i + (long)1024*1024] = h;
    p.out[w][i + (long)2*1024*1024] = l;
}

// ---------------- top-4 per row ----------------
__device__ __forceinline__ void ins4(float v, int id, float tv[4], int ti[4]) {
    if (v <= tv[3]) return;
    if (v > tv[0]) { tv[3]=tv[2]; ti[3]=ti[2]; tv[2]=tv[1]; ti[2]=ti[1];
                     tv[1]=tv[0]; ti[1]=ti[0]; tv[0]=v; ti[0]=id; }
    else if (v > tv[1]) { tv[3]=tv[2]; ti[3]=ti[2]; tv[2]=tv[1]; ti[2]=ti[1]; tv[1]=v; ti[1]=id; }
    else if (v > tv[2]) { tv[3]=tv[2]; ti[3]=ti[2]; tv[2]=v; ti[2]=id; }
    else { tv[3]=v; ti[3]=id; }
}

__global__ void __launch_bounds__(128)
topk_kernel(const float* __restrict__ logits, float* __restrict__ topv, int* __restrict__ topi)
{
    const int m = blockIdx.x;
    const float* p = logits + (long)m * Sdim;
    float tv[4] = {-1e30f,-1e30f,-1e30f,-1e30f};
    int   ti[4] = {-1,-1,-1,-1};
    for (int j = threadIdx.x; j < Sdim; j += 128) ins4(p[j], j, tv, ti);
    __shared__ float sv[128*4];
    __shared__ int   si[128*4];
#pragma unroll
    for (int j=0;j<4;j++){ sv[threadIdx.x*4+j]=tv[j]; si[threadIdx.x*4+j]=ti[j]; }
    __syncthreads();
    if (threadIdx.x == 0){
        float rv[4] = {-1e30f,-1e30f,-1e30f,-1e30f};
        int   ri[4] = {-1,-1,-1,-1};
        for (int c=0;c<128*4;c++) ins4(sv[c], si[c], rv, ri);
#pragma unroll
        for (int j=0;j<4;j++){ topv[m*4+j]=rv[j]; topi[m*4+j]=ri[j]; }
    }
}

// ---------------- softmax + gather-weighted V -> split bf16 ----------------
__global__ void __launch_bounds__(256)
route_kernel(const float* __restrict__ v, const float* __restrict__ topv,
             const int* __restrict__ topi, const float* __restrict__ temp,
             __nv_bfloat16* __restrict__ rs)
{
    const int m = blockIdx.x;
    const int b = m >> 12;
    const float t = temp[0];
    float v0 = topv[m*4+0], v1 = topv[m*4+1], v2 = topv[m*4+2], v3 = topv[m*4+3];
    float mx = fmaxf(fmaxf(v0,v1), fmaxf(v2,v3));
    float e0 = expf((v0-mx)/t), e1 = expf((v1-mx)/t);
    float e2 = expf((v2-mx)/t), e3 = expf((v3-mx)/t);
    float inv = 1.f/(e0+e1+e2+e3);
    e0*=inv; e1*=inv; e2*=inv; e3*=inv;

    const float* vb = v + (long)b*Sdim*Hdim;
    int i0=topi[m*4+0], i1=topi[m*4+1], i2=topi[m*4+2], i3=topi[m*4+3];
    const float4* r0 = reinterpret_cast<const float4*>(vb + (long)i0*Hdim);
    const float4* r1 = reinterpret_cast<const float4*>(vb + (long)i1*Hdim);
    const float4* r2 = reinterpret_cast<const float4*>(vb + (long)i2*Hdim);
    const float4* r3 = reinterpret_cast<const float4*>(vb + (long)i3*Hdim);

    int c = threadIdx.x;
    float4 a = r0[c], bb = r1[c], cc = r2[c], dd = r3[c];
    float o[4];
    o[0] = e0*a.x + e1*bb.x + e2*cc.x + e3*dd.x;
    o[1] = e0*a.y + e1*bb.y + e2*cc.y + e3*dd.y;
    o[2] = e0*a.z + e1*bb.z + e2*cc.z + e3*dd.z;
    o[3] = e0*a.w + e1*bb.w + e2*cc.w + e3*dd.w;
    long ob = (long)m*K3 + c*4;
#pragma unroll
    for (int j=0;j<4;j++){
        __nv_bfloat16 h,l; split2(o[j],h,l);
        rs[ob+j] = h; rs[ob+1024+j] = l; rs[ob+2048+j] = h;
    }
}

// ---------------- LayerNorm (+gelu) -> optional fp32 + split bf16 ----------------
template<int GELU>
__global__ void __launch_bounds__(256)
ln_kernel(const float* __restrict__ in, const float* __restrict__ g,
          const float* __restrict__ b, float* __restrict__ outf,
          __nv_bfloat16* __restrict__ outs)
{
    const int m = blockIdx.x;
    const int c = threadIdx.x;
    float4 x4 = reinterpret_cast<const float4*>(in + (long)m*Hdim)[c];
    float s  = x4.x + x4.y + x4.z + x4.w;
    float ss = x4.x*x4.x + x4.y*x4.y + x4.z*x4.z + x4.w*x4.w;
#pragma unroll
    for (int o=16;o>0;o>>=1){
        s  += __shfl_down_sync(0xffffffffu, s,  o);
        ss += __shfl_down_sync(0xffffffffu, ss, o);
    }
    __shared__ float red[2][8];
    int warp = c>>5, lane = c&31;
    if (lane==0){ red[0][warp]=s; red[1][warp]=ss; }
    __syncthreads();
    if (c==0){
        float S_=0.f, SS_=0.f;
#pragma unroll
        for (int w=0;w<8;w++){ S_+=red[0][w]; SS_+=red[1][w]; }
        red[0][0]=S_; red[1][0]=SS_;
    }
    __syncthreads();
    float mu  = red[0][0]*(1.f/Hdim);
    float var = red[1][0]*(1.f/Hdim) - mu*mu;
    float rs  = rsqrtf(var + LNEPS);
    float4 g4 = reinterpret_cast<const float4*>(g)[c];
    float4 b4 = reinterpret_cast<const float4*>(b)[c];
    float y[4];
    y[0] = (x4.x-mu)*rs*g4.x + b4.x;
    y[1] = (x4.y-mu)*rs*g4.y + b4.y;
    y[2] = (x4.z-mu)*rs*g4.z + b4.z;
    y[3] = (x4.w-mu)*rs*g4.w + b4.w;
    if (GELU){
#pragma unroll
        for (int j=0;j<4;j++) y[j] = 0.5f*y[j]*(1.f + erff(y[j]*0.70710678118f));
    }
    if (outf){
        float4 yo; yo.x=y[0]; yo.y=y[1]; yo.z=y[2]; yo.w=y[3];
        reinterpret_cast<float4*>(outf + (long)m*Hdim)[c] = yo;
    }
    long ob = (long)m*K3 + c*4;
#pragma unroll
    for (int j=0;j<4;j++){
        __nv_bfloat16 h,l; split2(y[j],h,l);
        outs[ob+j] = h; outs[ob+1024+j] = l; outs[ob+2048+j] = h;
    }
}

// ---------------- launch ----------------
extern "C" void kernel_launch(void* const* d_in, const int* in_sizes, int n_in,
                              void* d_out, int out_size)
{
    const float* x    = (const float*)d_in[0];
    const float* Wq   = (const float*)d_in[1];
    const float* bq   = (const float*)d_in[2];
    const float* Wk   = (const float*)d_in[3];
    const float* bk   = (const float*)d_in[4];
    const float* Wv   = (const float*)d_in[5];
    const float* bv   = (const float*)d_in[6];
    const float* Wc   = (const float*)d_in[7];
    const float* bc   = (const float*)d_in[8];
    const float* ln_g = (const float*)d_in[9];
    const float* ln_b = (const float*)d_in[10];
    const float* Wg1  = (const float*)d_in[11];
    const float* bg1  = (const float*)d_in[12];
    const float* gln_g= (const float*)d_in[13];
    const float* gln_b= (const float*)d_in[14];
    const float* Wg2  = (const float*)d_in[15];
    const float* bg2  = (const float*)d_in[16];
    const float* temp = (const float*)d_in[17];
    float* out = (float*)d_out;

    __nv_bfloat16 *xs_p, *qs_p, *ks_p, *rs_p, *cs_p, *hs_p, *ws_p;
    float *v_p, *logits_p, *topv_p, *cpre_p, *comb_p, *hpre_p;
    int *topi_p;
    cudaGetSymbolAddress((void**)&xs_p,    g_xs);
    cudaGetSymbolAddress((void**)&qs_p,    g_qs);
    cudaGetSymbolAddress((void**)&ks_p,    g_ks);
    cudaGetSymbolAddress((void**)&v_p,     g_v);
    cudaGetSymbolAddress((void**)&logits_p,g_logits);
    cudaGetSymbolAddress((void**)&topv_p,  g_topv);
    cudaGetSymbolAddress((void**)&topi_p,  g_topi);
    cudaGetSymbolAddress((void**)&rs_p,    g_rs);
    cudaGetSymbolAddress((void**)&cpre_p,  g_cpre);
    cudaGetSymbolAddress((void**)&comb_p,  g_comb);
    cudaGetSymbolAddress((void**)&cs_p,    g_cs);
    cudaGetSymbolAddress((void**)&hpre_p,  g_hpre);
    cudaGetSymbolAddress((void**)&hs_p,    g_hs);
    cudaGetSymbolAddress((void**)&ws_p,    g_ws);

    const long WSZ = (long)K3*Hdim;
    __nv_bfloat16 *wq_p = ws_p,       *wk_p = ws_p + WSZ,   *wv_p = ws_p + 2*WSZ,
                  *wc_p = ws_p+3*WSZ, *wg1a_p = ws_p+4*WSZ, *wg1b_p = ws_p+5*WSZ,
                  *wg2_p = ws_p+6*WSZ;

    split_x_kernel<<<MTOT*Hdim/256, 256>>>(x, xs_p);
    WPtrs wp;
    wp.in[0]=Wq; wp.in[1]=Wk; wp.in[2]=Wv; wp.in[3]=Wc;
    wp.in[4]=Wg1; wp.in[5]=Wg1 + (long)Hdim*Hdim; wp.in[6]=Wg2;
    wp.out[0]=wq_p; wp.out[1]=wk_p; wp.out[2]=wv_p; wp.out[3]=wc_p;
    wp.out[4]=wg1a_p; wp.out[5]=wg1b_p; wp.out[6]=wg2_p;
    split_w_kernel<<<dim3(Hdim*Hdim/256,1,7), 256>>>(wp);

    dim3 gNN(Hdim/BNt, MTOT/BMt, 1);       // (8, 64)
    dim3 gNT(Sdim/BNt, Sdim/BMt, Bdim);    // (32, 32, 2)

    const int smemNN = NSTAGE*(BMt*ASTR*2 + BKt*BSTRNN*2);   // 75776
    const int smemNT = NSTAGE*(BMt*ASTR*2 + BNt*ASTR*2);     // 81920

    cudaFuncSetAttribute((const void*)mma_gemm<false,5>, cudaFuncAttributeMaxDynamicSharedMemorySize, smemNN);
    cudaFuncSetAttribute((const void*)mma_gemm<false,6>, cudaFuncAttributeMaxDynamicSharedMemorySize, smemNN);
    cudaFuncSetAttribute((const void*)mma_gemm<false,0>, cudaFuncAttributeMaxDynamicSharedMemorySize, smemNN);
    cudaFuncSetAttribute((const void*)mma_gemm<false,1>, cudaFuncAttributeMaxDynamicSharedMemorySize, smemNN);
    cudaFuncSetAttribute((const void*)mma_gemm<false,3>, cudaFuncAttributeMaxDynamicSharedMemorySize, smemNN);
    cudaFuncSetAttribute((const void*)mma_gemm<true,2>,  cudaFuncAttributeMaxDynamicSharedMemorySize, smemNT);

    // q (A-split out), k (B-split out), v (fp32 out)
    mma_gemm<false,5><<<gNN,256,smemNN>>>(xs_p, wq_p, bq, nullptr, nullptr, qs_p, K3, Hdim, 0,0,0, 1.f);
    mma_gemm<false,6><<<gNN,256,smemNN>>>(xs_p, wk_p, bk, nullptr, nullptr, ks_p, K3, Hdim, 0,0,0, 1.f);
    mma_gemm<false,0><<<gNN,256,smemNN>>>(xs_p, wv_p, bv, nullptr, nullptr, v_p,  K3, Hdim, 0,0,0, 1.f);

    // logits = q @ k^T / 8  (bf16x3, NT, K=3072)
    mma_gemm<true,2><<<gNT,256,smemNT>>>(qs_p, ks_p, nullptr, nullptr, nullptr, logits_p,
                                  K3, Sdim, (long)Sdim*K3, (long)Sdim*K3,
                                  (long)Sdim*Sdim, INV_SCALE);

    topk_kernel<<<MTOT,128>>>(logits_p, topv_p, topi_p);
    route_kernel<<<MTOT,256>>>(v_p, topv_p, topi_p, temp, rs_p);

    // combined = LN(routed @ Wc + bc)
    mma_gemm<false,0><<<gNN,256,smemNN>>>(rs_p, wc_p, bc, nullptr, nullptr, cpre_p, K3, Hdim, 0,0,0, 1.f);
    ln_kernel<0><<<MTOT,256>>>(cpre_p, ln_g, ln_b, comb_p, cs_p);

    // hpre = x @ Wg1a + bg1 + combined @ Wg1b
    mma_gemm<false,0><<<gNN,256,smemNN>>>(xs_p, wg1a_p, bg1, nullptr, nullptr, hpre_p, K3, Hdim, 0,0,0, 1.f);
    mma_gemm<false,1><<<gNN,256,smemNN>>>(cs_p, wg1b_p, nullptr, nullptr, nullptr, hpre_p, K3, Hdim, 0,0,0, 1.f);

    // h = gelu(LN(hpre))
    ln_kernel<1><<<MTOT,256>>>(hpre_p, gln_g, gln_b, nullptr, hs_p);

    // out = sigmoid(h @ Wg2 + bg2) * combined + (1-s) * x
    mma_gemm<false,3><<<gNN,256,smemNN>>>(hs_p, wg2_p, bg2, comb_p, x, out, K3, Hdim, 0,0,0, 1.f);
}

// round 6
// speedup vs baseline: 2.7682x; 1.2511x over previous
#include <cuda_runtime.h>
#include <cuda_bf16.h>
#include <math.h>
#include <stdint.h>

#define Hdim 1024
#define Bdim 2
#define Sdim 4096
#define MTOT 8192
#define K3 3072
#define K6 6144
#define INV_SCALE 0.125f
#define LNEPS 1e-5f

// ---------------- scratch ----------------
__device__ __nv_bfloat16 g_xcs[(long)MTOT*K6];     // [x_split | combined_split], stride K6
__device__ float g_q[(long)MTOT*Hdim];
__device__ float g_k[(long)MTOT*Hdim];
__device__ float g_v[(long)MTOT*Hdim];
__device__ __nv_bfloat16 g_qb[(long)MTOT*Hdim];
__device__ __nv_bfloat16 g_kb[(long)MTOT*Hdim];
__device__ float g_logits[(long)Bdim*Sdim*Sdim];
__device__ float g_topv[MTOT*4];
__device__ int   g_topi[MTOT*4];
__device__ __nv_bfloat16 g_rs[(long)MTOT*K3];
__device__ float g_cpre[(long)MTOT*Hdim];
__device__ float g_comb[(long)MTOT*Hdim];
__device__ float g_hpre[(long)MTOT*Hdim];
__device__ __nv_bfloat16 g_hs[(long)MTOT*K3];
__device__ __nv_bfloat16 g_wsK3[5][(long)K3*Hdim];  // wq,wk,wv,wc,wg2  [3K,N]
__device__ __nv_bfloat16 g_wg1cat[(long)K6*Hdim];   // [6K,N] = [wg1a split ; wg1b split]

// ---------------- helpers ----------------
__device__ __forceinline__ uint32_t s2u(const void* p){ return (uint32_t)__cvta_generic_to_shared(p); }

__device__ __forceinline__ void ldsm4(uint32_t& r0,uint32_t& r1,uint32_t& r2,uint32_t& r3, uint32_t a){
    asm volatile("ldmatrix.sync.aligned.m8n8.x4.shared.b16 {%0,%1,%2,%3},[%4];"
        :"=r"(r0),"=r"(r1),"=r"(r2),"=r"(r3):"r"(a));
}
__device__ __forceinline__ void ldsm4t(uint32_t& r0,uint32_t& r1,uint32_t& r2,uint32_t& r3, uint32_t a){
    asm volatile("ldmatrix.sync.aligned.m8n8.x4.trans.shared.b16 {%0,%1,%2,%3},[%4];"
        :"=r"(r0),"=r"(r1),"=r"(r2),"=r"(r3):"r"(a));
}
__device__ __forceinline__ void mma16816(float* c, const uint32_t* a, const uint32_t* b){
    asm volatile("mma.sync.aligned.m16n8k16.row.col.f32.bf16.bf16.f32 "
        "{%0,%1,%2,%3},{%4,%5,%6,%7},{%8,%9},{%0,%1,%2,%3};"
        : "+f"(c[0]),"+f"(c[1]),"+f"(c[2]),"+f"(c[3])
        : "r"(a[0]),"r"(a[1]),"r"(a[2]),"r"(a[3]),"r"(b[0]),"r"(b[1]));
}
__device__ __forceinline__ void cpa16(uint32_t dst, const void* src){
    asm volatile("cp.async.cg.shared.global [%0], [%1], 16;" :: "r"(dst), "l"(src));
}
__device__ __forceinline__ void cpa_commit(){ asm volatile("cp.async.commit_group;"); }
template<int N_> __device__ __forceinline__ void cpa_wait(){ asm volatile("cp.async.wait_group %0;"::"n"(N_)); }

__device__ __forceinline__ void split2(float v, __nv_bfloat16& h, __nv_bfloat16& l){
    h = __float2bfloat16(v);
    l = __float2bfloat16(v - __bfloat162float(h));
}

// ---------------- bf16 tensor-core GEMM, 4-stage cp.async pipeline ----------------
// BM=128, BN=128, BK=32, 256 threads (8 warps: 2x4), warp tile 64x32.
// TRANSB=false: B is [K,N] row-major (ldb = N).  TRANSB=true: B is [N,K] row-major (ldb = row stride).
// lda = A row stride (>= K).
// MODE 0: fp32 C = acc + bias[n]
// MODE 2: fp32 C = acc * alpha
// MODE 3: sg = sigmoid(acc+bias); C = sg*E1 + (1-sg)*E2
#define BMt 128
#define BNt 128
#define BKt 32
#define ASTR 40      // 32+8 elems: conflict-free ldmatrix
#define BSTRNN 136   // 128+8 elems
#define NSTAGE 4

template<bool TRANSB, int MODE>
__global__ void __launch_bounds__(256)
mma_gemm(const __nv_bfloat16* __restrict__ A, const __nv_bfloat16* __restrict__ B,
         const float* __restrict__ bias, const float* __restrict__ E1,
         const float* __restrict__ E2, void* __restrict__ Cptr,
         int K, int N, int lda, int ldb, long sA, long sB, long sC, float alpha)
{
    constexpr int ASTAGE = BMt*ASTR*2;                          // bytes
    constexpr int BSTAGE = TRANSB ? (BNt*ASTR*2) : (BKt*BSTRNN*2);
    extern __shared__ char sm[];
    const uint32_t aBase = s2u(sm);
    const uint32_t bBase = aBase + NSTAGE*ASTAGE;

    const int tid  = threadIdx.x;
    const int lane = tid & 31;
    const int warp = tid >> 5;
    const int wm = warp & 1;
    const int wn = warp >> 1;
    const int m0 = blockIdx.y * BMt;
    const int n0 = blockIdx.x * BNt;

    const __nv_bfloat16* Ab = A + blockIdx.z*sA + (long)m0*lda;
    const __nv_bfloat16* Bb = TRANSB ? (B + blockIdx.z*sB + (long)n0*ldb) : (B + n0);

    float acc[4][4][4];
#pragma unroll
    for (int i=0;i<4;i++)
#pragma unroll
        for (int j=0;j<4;j++)
#pragma unroll
            for (int h=0;h<4;h++) acc[i][j][h] = 0.f;

    auto copyA = [&](int st, int k0){
        uint32_t base = aBase + st*ASTAGE;
#pragma unroll
        for (int l=0;l<2;l++){
            int id = tid + l*256; int r = id>>2; int c = (id&3)*8;
            cpa16(base + (r*ASTR + c)*2, Ab + (long)r*lda + k0 + c);
        }
    };
    auto copyB = [&](int st, int k0){
        uint32_t base = bBase + st*BSTAGE;
        if (TRANSB){
#pragma unroll
            for (int l=0;l<2;l++){
                int id = tid + l*256; int r = id>>2; int c = (id&3)*8;
                cpa16(base + (r*ASTR + c)*2, Bb + (long)r*ldb + k0 + c);
            }
        } else {
#pragma unroll
            for (int l=0;l<2;l++){
                int id = tid + l*256; int r = id>>4; int c = (id&15)*8;
                cpa16(base + (r*BSTRNN + c)*2, Bb + (long)(k0+r)*ldb + c);
            }
        }
    };

    const int nt = K / BKt;
#pragma unroll
    for (int s=0; s<NSTAGE-1; s++){
        copyA(s, s*BKt); copyB(s, s*BKt); cpa_commit();
    }

    int buf = 0;
    for (int t = 0; t < nt; t++){
        cpa_wait<NSTAGE-2>();
        __syncthreads();
        const uint32_t aS = aBase + buf*ASTAGE;
        const uint32_t bS = bBase + buf*BSTAGE;
#pragma unroll
        for (int ks=0; ks<2; ks++){
            uint32_t af[4][4];
#pragma unroll
            for (int mi=0; mi<4; mi++){
                int row = wm*64 + mi*16 + (lane&15);
                int col = ks*16 + ((lane>>4)<<3);
                ldsm4(af[mi][0],af[mi][1],af[mi][2],af[mi][3],
                      aS + (row*ASTR + col)*2);
            }
            uint32_t bf[4][2];
            if (TRANSB){
#pragma unroll
                for (int nj=0; nj<2; nj++){
                    int g = lane>>3;
                    int row = wn*32 + nj*16 + ((g>>1)<<3) + (lane&7);
                    int col = ks*16 + ((g&1)<<3);
                    uint32_t r0,r1,r2,r3;
                    ldsm4(r0,r1,r2,r3, bS + (row*ASTR + col)*2);
                    bf[nj*2][0]=r0; bf[nj*2][1]=r1; bf[nj*2+1][0]=r2; bf[nj*2+1][1]=r3;
                }
            } else {
#pragma unroll
                for (int nj=0; nj<2; nj++){
                    int row = ks*16 + (lane&15);
                    int col = wn*32 + nj*16 + ((lane>>4)<<3);
                    uint32_t r0,r1,r2,r3;
                    ldsm4t(r0,r1,r2,r3, bS + (row*BSTRNN + col)*2);
                    bf[nj*2][0]=r0; bf[nj*2][1]=r1; bf[nj*2+1][0]=r2; bf[nj*2+1][1]=r3;
                }
            }
#pragma unroll
            for (int mi=0;mi<4;mi++)
#pragma unroll
                for (int ni=0;ni<4;ni++)
                    mma16816(acc[mi][ni], af[mi], bf[ni]);
        }
        int tn = t + NSTAGE-1;
        if (tn < nt){
            int st = buf + NSTAGE-1; if (st >= NSTAGE) st -= NSTAGE;
            copyA(st, tn*BKt); copyB(st, tn*BKt);
        }
        cpa_commit();
        buf = (buf+1 == NSTAGE) ? 0 : buf+1;
    }

    const long cb = blockIdx.z*sC;
#pragma unroll
    for (int mi=0;mi<4;mi++){
#pragma unroll
        for (int ni=0;ni<4;ni++){
#pragma unroll
            for (int h=0; h<2; h++){
                int row = m0 + wm*64 + mi*16 + (lane>>2) + h*8;
                int col = n0 + wn*32 + ni*8 + (lane&3)*2;
                long idx = cb + (long)row*N + col;
                float v0 = acc[mi][ni][h*2], v1 = acc[mi][ni][h*2+1];
                if (MODE == 0){
                    float* C = (float*)Cptr;
                    C[idx]   = v0 + bias[col];
                    C[idx+1] = v1 + bias[col+1];
                } else if (MODE == 2){
                    float2 o; o.x = v0*alpha; o.y = v1*alpha;
                    *reinterpret_cast<float2*>((float*)Cptr + idx) = o;
                } else {
                    float* C = (float*)Cptr;
                    float p0 = v0 + bias[col],   p1 = v1 + bias[col+1];
                    float s0 = 1.f/(1.f+expf(-p0)), s1 = 1.f/(1.f+expf(-p1));
                    C[idx]   = s0*E1[idx]   + (1.f-s0)*E2[idx];
                    C[idx+1] = s1*E1[idx+1] + (1.f-s1)*E2[idx+1];
                }
            }
        }
    }
}

// ---------------- split x into xcs first K3 cols (A-layout hi|lo|hi, stride K6) ----------------
__global__ void __launch_bounds__(256)
split_x_kernel(const float* __restrict__ in, __nv_bfloat16* __restrict__ out)
{
    long i = (long)blockIdx.x*256 + threadIdx.x;
    int m = (int)(i >> 10), k = (int)(i & 1023);
    float v = in[i];
    __nv_bfloat16 h,l; split2(v,h,l);
    long ob = (long)m*K6 + k;
    out[ob] = h; out[ob+1024] = l; out[ob+2048] = h;
}

// ---------------- weight split (B-layout [K,N] -> [3K,N] hi;hi;lo) ----------------
struct WPtrs { const float* in[7]; __nv_bfloat16* out[7]; };
__global__ void __launch_bounds__(256)
split_w_kernel(WPtrs p)
{
    int w = blockIdx.z;
    long i = (long)blockIdx.x*256 + threadIdx.x;   // over 1024*1024
    float v = p.in[w][i];
    __nv_bfloat16 h,l; split2(v,h,l);
    p.out[w][i] = h;
    p.out[w][i + (long)1024*1024] = h;
    p.out[w][i + (long)2*1024*1024] = l;
}

// ---------------- fp32 q,k -> bf16 ----------------
__global__ void __launch_bounds__(256)
conv_kernel(const float* __restrict__ q, const float* __restrict__ k,
            __nv_bfloat16* __restrict__ qb, __nv_bfloat16* __restrict__ kb)
{
    long i = (long)blockIdx.x*256 + threadIdx.x;
    qb[i] = __float2bfloat16(q[i]);
    kb[i] = __float2bfloat16(k[i]);
}

// ---------------- top-k helpers ----------------
__device__ __forceinline__ void ins4(float v, int id, float tv[4], int ti[4]) {
    if (v <= tv[3]) return;
    if (v > tv[0]) { tv[3]=tv[2]; ti[3]=ti[2]; tv[2]=tv[1]; ti[2]=ti[1];
                     tv[1]=tv[0]; ti[1]=ti[0]; tv[0]=v; ti[0]=id; }
    else if (v > tv[1]) { tv[3]=tv[2]; ti[3]=ti[2]; tv[2]=tv[1]; ti[2]=ti[1]; tv[1]=v; ti[1]=id; }
    else if (v > tv[2]) { tv[3]=tv[2]; ti[3]=ti[2]; tv[2]=v; ti[2]=id; }
    else { tv[3]=v; ti[3]=id; }
}

__device__ __forceinline__ void ins8(float v, int id, float* tv, int* ti) {
    if (v <= tv[7]) return;
    tv[7] = v; ti[7] = id;
#pragma unroll
    for (int j=7; j>0; j--){
        if (tv[j] > tv[j-1]){
            float tf=tv[j]; tv[j]=tv[j-1]; tv[j-1]=tf;
            int tii=ti[j]; ti[j]=ti[j-1]; ti[j-1]=tii;
        }
    }
}

// ---------------- top-8 approx + exact fp32 rescue -> top-4 ----------------
__global__ void __launch_bounds__(128)
topk_rescue(const float* __restrict__ logits, const float* __restrict__ q,
            const float* __restrict__ k, float* __restrict__ topv, int* __restrict__ topi)
{
    const int m = blockIdx.x;
    const int tid = threadIdx.x;
    const float* p = logits + (long)m * Sdim;

    float tv[8]; int ti[8];
#pragma unroll
    for (int j=0;j<8;j++){ tv[j]=-1e30f; ti[j]=-1; }
    for (int j = tid; j < Sdim; j += 128) ins8(p[j], j, tv, ti);

    __shared__ float sv[128*8];
    __shared__ int   si[128*8];
#pragma unroll
    for (int j=0;j<8;j++){ sv[tid*8+j]=tv[j]; si[tid*8+j]=ti[j]; }
    __syncthreads();

    // stage 2: 32 lanes each merge 4 thread-lists
    if (tid < 32){
        float mv[8]; int mi[8];
#pragma unroll
        for (int j=0;j<8;j++){ mv[j]=-1e30f; mi[j]=-1; }
        for (int s=0;s<4;s++){
            int base = (tid + s*32)*8;
#pragma unroll
            for (int j=0;j<8;j++) ins8(sv[base+j], si[base+j], mv, mi);
        }
#pragma unroll
        for (int j=0;j<8;j++){ sv[tid*8+j]=mv[j]; si[tid*8+j]=mi[j]; }
    }
    __syncthreads();

    __shared__ int cands[8];
    if (tid == 0){
        float rv[8]; int ri[8];
#pragma unroll
        for (int j=0;j<8;j++){ rv[j]=-1e30f; ri[j]=-1; }
        for (int c=0;c<32*8;c++) ins8(sv[c], si[c], rv, ri);
#pragma unroll
        for (int j=0;j<8;j++) cands[j] = ri[j];
    }
    __syncthreads();

    // exact fp32 rescoring of 8 candidates
    __shared__ float qrow[Hdim];
    const float* qr = q + (long)m*Hdim;
    for (int j = tid; j < Hdim; j += 128) qrow[j] = qr[j];
    __syncthreads();

    const int b = m >> 12;
    const int warp = tid >> 5, lane = tid & 31;
    __shared__ float exact[8];
#pragma unroll
    for (int cc=0; cc<2; cc++){
        int c = warp*2 + cc;
        const float* kr = k + ((long)b*Sdim + cands[c])*Hdim;
        float s = 0.f;
        for (int j = lane; j < Hdim; j += 32) s += qrow[j]*kr[j];
#pragma unroll
        for (int o=16;o>0;o>>=1) s += __shfl_down_sync(0xffffffffu, s, o);
        if (lane == 0) exact[c] = s * INV_SCALE;
    }
    __syncthreads();

    if (tid == 0){
        float rv[4] = {-1e30f,-1e30f,-1e30f,-1e30f};
        int   ri[4] = {-1,-1,-1,-1};
#pragma unroll
        for (int c=0;c<8;c++) ins4(exact[c], cands[c], rv, ri);
#pragma unroll
        for (int j=0;j<4;j++){ topv[m*4+j]=rv[j]; topi[m*4+j]=ri[j]; }
    }
}

// ---------------- softmax + gather-weighted V -> split bf16 (A-layout, stride K3) ----------------
__global__ void __launch_bounds__(256)
route_kernel(const float* __restrict__ v, const float* __restrict__ topv,
             const int* __restrict__ topi, const float* __restrict__ temp,
             __nv_bfloat16* __restrict__ rs)
{
    const int m = blockIdx.x;
    const int b = m >> 12;
    const float t = temp[0];
    float v0 = topv[m*4+0], v1 = topv[m*4+1], v2 = topv[m*4+2], v3 = topv[m*4+3];
    float mx = fmaxf(fmaxf(v0,v1), fmaxf(v2,v3));
    float e0 = expf((v0-mx)/t), e1 = expf((v1-mx)/t);
    float e2 = expf((v2-mx)/t), e3 = expf((v3-mx)/t);
    float inv = 1.f/(e0+e1+e2+e3);
    e0*=inv; e1*=inv; e2*=inv; e3*=inv;

    const float* vb = v + (long)b*Sdim*Hdim;
    int i0=topi[m*4+0], i1=topi[m*4+1], i2=topi[m*4+2], i3=topi[m*4+3];
    const float4* r0 = reinterpret_cast<const float4*>(vb + (long)i0*Hdim);
    const float4* r1 = reinterpret_cast<const float4*>(vb + (long)i1*Hdim);
    const float4* r2 = reinterpret_cast<const float4*>(vb + (long)i2*Hdim);
    const float4* r3 = reinterpret_cast<const float4*>(vb + (long)i3*Hdim);

    int c = threadIdx.x;
    float4 a = r0[c], bb = r1[c], cc = r2[c], dd = r3[c];
    float o[4];
    o[0] = e0*a.x + e1*bb.x + e2*cc.x + e3*dd.x;
    o[1] = e0*a.y + e1*bb.y + e2*cc.y + e3*dd.y;
    o[2] = e0*a.z + e1*bb.z + e2*cc.z + e3*dd.z;
    o[3] = e0*a.w + e1*bb.w + e2*cc.w + e3*dd.w;
    long ob = (long)m*K3 + c*4;
#pragma unroll
    for (int j=0;j<4;j++){
        __nv_bfloat16 h,l; split2(o[j],h,l);
        rs[ob+j] = h; rs[ob+1024+j] = l; rs[ob+2048+j] = h;
    }
}

// ---------------- LayerNorm (+gelu) -> optional fp32 + split bf16 (A-layout) ----------------
template<int GELU>
__global__ void __launch_bounds__(256)
ln_kernel(const float* __restrict__ in, const float* __restrict__ g,
          const float* __restrict__ b, float* __restrict__ outf,
          __nv_bfloat16* __restrict__ outs, int ostride)
{
    const int m = blockIdx.x;
    const int c = threadIdx.x;
    float4 x4 = reinterpret_cast<const float4*>(in + (long)m*Hdim)[c];
    float s  = x4.x + x4.y + x4.z + x4.w;
    float ss = x4.x*x4.x + x4.y*x4.y + x4.z*x4.z + x4.w*x4.w;
#pragma unroll
    for (int o=16;o>0;o>>=1){
        s  += __shfl_down_sync(0xffffffffu, s,  o);
        ss += __shfl_down_sync(0xffffffffu, ss, o);
    }
    __shared__ float red[2][8];
    int warp = c>>5, lane = c&31;
    if (lane==0){ red[0][warp]=s; red[1][warp]=ss; }
    __syncthreads();
    if (c==0){
        float S_=0.f, SS_=0.f;
#pragma unroll
        for (int w=0;w<8;w++){ S_+=red[0][w]; SS_+=red[1][w]; }
        red[0][0]=S_; red[1][0]=SS_;
    }
    __syncthreads();
    float mu  = red[0][0]*(1.f/Hdim);
    float var = red[1][0]*(1.f/Hdim) - mu*mu;
    float rsd = rsqrtf(var + LNEPS);
    float4 g4 = reinterpret_cast<const float4*>(g)[c];
    float4 b4 = reinterpret_cast<const float4*>(b)[c];
    float y[4];
    y[0] = (x4.x-mu)*rsd*g4.x + b4.x;
    y[1] = (x4.y-mu)*rsd*g4.y + b4.y;
    y[2] = (x4.z-mu)*rsd*g4.z + b4.z;
    y[3] = (x4.w-mu)*rsd*g4.w + b4.w;
    if (GELU){
#pragma unroll
        for (int j=0;j<4;j++) y[j] = 0.5f*y[j]*(1.f + erff(y[j]*0.70710678118f));
    }
    if (outf){
        float4 yo; yo.x=y[0]; yo.y=y[1]; yo.z=y[2]; yo.w=y[3];
        reinterpret_cast<float4*>(outf + (long)m*Hdim)[c] = yo;
    }
    long ob = (long)m*ostride + c*4;
#pragma unroll
    for (int j=0;j<4;j++){
        __nv_bfloat16 h,l; split2(y[j],h,l);
        outs[ob+j] = h; outs[ob+1024+j] = l; outs[ob+2048+j] = h;
    }
}

// ---------------- launch ----------------
extern "C" void kernel_launch(void* const* d_in, const int* in_sizes, int n_in,
                              void* d_out, int out_size)
{
    const float* x    = (const float*)d_in[0];
    const float* Wq   = (const float*)d_in[1];
    const float* bq   = (const float*)d_in[2];
    const float* Wk   = (const float*)d_in[3];
    const float* bk   = (const float*)d_in[4];
    const float* Wv   = (const float*)d_in[5];
    const float* bv   = (const float*)d_in[6];
    const float* Wc   = (const float*)d_in[7];
    const float* bc   = (const float*)d_in[8];
    const float* ln_g = (const float*)d_in[9];
    const float* ln_b = (const float*)d_in[10];
    const float* Wg1  = (const float*)d_in[11];
    const float* bg1  = (const float*)d_in[12];
    const float* gln_g= (const float*)d_in[13];
    const float* gln_b= (const float*)d_in[14];
    const float* Wg2  = (const float*)d_in[15];
    const float* bg2  = (const float*)d_in[16];
    const float* temp = (const float*)d_in[17];
    float* out = (float*)d_out;

    __nv_bfloat16 *xcs_p, *qb_p, *kb_p, *rs_p, *hs_p, *wsK3_p, *wg1cat_p;
    float *q_p, *k_p, *v_p, *logits_p, *topv_p, *cpre_p, *comb_p, *hpre_p;
    int *topi_p;
    cudaGetSymbolAddress((void**)&xcs_p,   g_xcs);
    cudaGetSymbolAddress((void**)&q_p,     g_q);
    cudaGetSymbolAddress((void**)&k_p,     g_k);
    cudaGetSymbolAddress((void**)&v_p,     g_v);
    cudaGetSymbolAddress((void**)&qb_p,    g_qb);
    cudaGetSymbolAddress((void**)&kb_p,    g_kb);
    cudaGetSymbolAddress((void**)&logits_p,g_logits);
    cudaGetSymbolAddress((void**)&topv_p,  g_topv);
    cudaGetSymbolAddress((void**)&topi_p,  g_topi);
    cudaGetSymbolAddress((void**)&rs_p,    g_rs);
    cudaGetSymbolAddress((void**)&cpre_p,  g_cpre);
    cudaGetSymbolAddress((void**)&comb_p,  g_comb);
    cudaGetSymbolAddress((void**)&hpre_p,  g_hpre);
    cudaGetSymbolAddress((void**)&hs_p,    g_hs);
    cudaGetSymbolAddress((void**)&wsK3_p,  g_wsK3);
    cudaGetSymbolAddress((void**)&wg1cat_p,g_wg1cat);

    const long WSZ = (long)K3*Hdim;
    __nv_bfloat16 *wq_p = wsK3_p,       *wk_p = wsK3_p + WSZ, *wv_p = wsK3_p + 2*WSZ,
                  *wc_p = wsK3_p+3*WSZ, *wg2_p = wsK3_p+4*WSZ;

    // splits
    split_x_kernel<<<MTOT*Hdim/256, 256>>>(x, xcs_p);
    WPtrs wp;
    wp.in[0]=Wq;  wp.out[0]=wq_p;
    wp.in[1]=Wk;  wp.out[1]=wk_p;
    wp.in[2]=Wv;  wp.out[2]=wv_p;
    wp.in[3]=Wc;  wp.out[3]=wc_p;
    wp.in[4]=Wg1;                     wp.out[4]=wg1cat_p;               // rows 0..3071
    wp.in[5]=Wg1 + (long)Hdim*Hdim;   wp.out[5]=wg1cat_p + K3*(long)Hdim; // rows 3072..6143
    wp.in[6]=Wg2; wp.out[6]=wg2_p;
    split_w_kernel<<<dim3(Hdim*Hdim/256,1,7), 256>>>(wp);

    dim3 gNN(Hdim/BNt, MTOT/BMt, 1);       // (8, 64)
    dim3 gNT(Sdim/BNt, Sdim/BMt, Bdim);    // (32, 32, 2)

    const int smemNN = NSTAGE*(BMt*ASTR*2 + BKt*BSTRNN*2);   // 75776
    const int smemNT = NSTAGE*(BMt*ASTR*2 + BNt*ASTR*2);     // 81920

    cudaFuncSetAttribute((const void*)mma_gemm<false,0>, cudaFuncAttributeMaxDynamicSharedMemorySize, smemNN);
    cudaFuncSetAttribute((const void*)mma_gemm<false,3>, cudaFuncAttributeMaxDynamicSharedMemorySize, smemNN);
    cudaFuncSetAttribute((const void*)mma_gemm<true,2>,  cudaFuncAttributeMaxDynamicSharedMemorySize, smemNT);

    // q, k, v (fp32 out, bf16x3 K=3072)
    mma_gemm<false,0><<<gNN,256,smemNN>>>(xcs_p, wq_p, bq, nullptr, nullptr, q_p, K3, Hdim, K6, Hdim, 0,0,0, 1.f);
    mma_gemm<false,0><<<gNN,256,smemNN>>>(xcs_p, wk_p, bk, nullptr, nullptr, k_p, K3, Hdim, K6, Hdim, 0,0,0, 1.f);
    mma_gemm<false,0><<<gNN,256,smemNN>>>(xcs_p, wv_p, bv, nullptr, nullptr, v_p, K3, Hdim, K6, Hdim, 0,0,0, 1.f);

    // bf16 copies of q,k for approx logits
    conv_kernel<<<MTOT*Hdim/256, 256>>>(q_p, k_p, qb_p, kb_p);

    // approx logits = qb @ kb^T / 8  (single bf16 pass, K=1024)
    mma_gemm<true,2><<<gNT,256,smemNT>>>(qb_p, kb_p, nullptr, nullptr, nullptr, logits_p,
                                  Hdim, Sdim, Hdim, Hdim,
                                  (long)Sdim*Hdim, (long)Sdim*Hdim, (long)Sdim*Sdim, INV_SCALE);

    // top-8 approx -> exact fp32 rescue -> top-4
    topk_rescue<<<MTOT,128>>>(logits_p, q_p, k_p, topv_p, topi_p);
    route_kernel<<<MTOT,256>>>(v_p, topv_p, topi_p, temp, rs_p);

    // combined = LN(routed @ Wc + bc); split into xcs second half
    mma_gemm<false,0><<<gNN,256,smemNN>>>(rs_p, wc_p, bc, nullptr, nullptr, cpre_p, K3, Hdim, K3, Hdim, 0,0,0, 1.f);
    ln_kernel<0><<<MTOT,256>>>(cpre_p, ln_g, ln_b, comb_p, xcs_p + K3, K6);

    // hpre = [x|combined] @ Wg1cat + bg1  (single K=6144 pass)
    mma_gemm<false,0><<<gNN,256,smemNN>>>(xcs_p, wg1cat_p, bg1, nullptr, nullptr, hpre_p, K6, Hdim, K6, Hdim, 0,0,0, 1.f);

    // h = gelu(LN(hpre))
    ln_kernel<1><<<MTOT,256>>>(hpre_p, gln_g, gln_b, nullptr, hs_p, K3);

    // out = sigmoid(h @ Wg2 + bg2) * combined + (1-s) * x
    mma_gemm<false,3><<<gNN,256,smemNN>>>(hs_p, wg2_p, bg2, comb_p, x, out, K3, Hdim, K3, Hdim, 0,0,0, 1.f);
}

// round 7
// speedup vs baseline: 4.3172x; 1.5595x over previous
#include <cuda_runtime.h>
#include <cuda_bf16.h>
#include <cuda_fp16.h>
#include <math.h>
#include <stdint.h>

#define Hdim 1024
#define Bdim 2
#define Sdim 4096
#define MTOT 8192
#define K2 2048
#define K3 3072
#define INV_SCALE 0.125f
#define LNEPS 1e-5f

// ---------------- scratch ----------------
__device__ __nv_bfloat16 g_xs[(long)MTOT*K3];      // x split hi|lo|hi (for q,k GEMMs)
__device__ __half g_xcat[(long)MTOT*K2];           // [x_f16 | combined_f16], stride 2048
__device__ float g_q[(long)MTOT*Hdim];
__device__ float g_k[(long)MTOT*Hdim];
__device__ float g_v[(long)MTOT*Hdim];
__device__ __half g_qh[(long)MTOT*Hdim];
__device__ __half g_kh[(long)MTOT*Hdim];
__device__ float g_logits[(long)Bdim*Sdim*Sdim];
__device__ float g_topv[MTOT*4];
__device__ int   g_topi[MTOT*4];
__device__ __half g_rh[(long)MTOT*Hdim];           // routed fp16
__device__ float g_cpre[(long)MTOT*Hdim];
__device__ float g_comb[(long)MTOT*Hdim];
__device__ float g_hpre[(long)MTOT*Hdim];
__device__ __half g_hs[(long)MTOT*Hdim];           // gelu(LN) fp16
__device__ __nv_bfloat16 g_wqk[2][(long)K3*Hdim];  // wq,wk split [3K,N]
__device__ __half g_wh[3][(long)Hdim*Hdim];        // wv,wc,wg2 fp16 [K,N]
__device__ __half g_wg1h[(long)K2*Hdim];           // wg1 fp16 [2K,N]

// ---------------- helpers ----------------
__device__ __forceinline__ uint32_t s2u(const void* p){ return (uint32_t)__cvta_generic_to_shared(p); }

__device__ __forceinline__ void ldsm4(uint32_t& r0,uint32_t& r1,uint32_t& r2,uint32_t& r3, uint32_t a){
    asm volatile("ldmatrix.sync.aligned.m8n8.x4.shared.b16 {%0,%1,%2,%3},[%4];"
        :"=r"(r0),"=r"(r1),"=r"(r2),"=r"(r3):"r"(a));
}
__device__ __forceinline__ void ldsm4t(uint32_t& r0,uint32_t& r1,uint32_t& r2,uint32_t& r3, uint32_t a){
    asm volatile("ldmatrix.sync.aligned.m8n8.x4.trans.shared.b16 {%0,%1,%2,%3},[%4];"
        :"=r"(r0),"=r"(r1),"=r"(r2),"=r"(r3):"r"(a));
}
template<bool HALF>
__device__ __forceinline__ void mma16816(float* c, const uint32_t* a, const uint32_t* b){
    if (HALF)
        asm volatile("mma.sync.aligned.m16n8k16.row.col.f32.f16.f16.f32 "
            "{%0,%1,%2,%3},{%4,%5,%6,%7},{%8,%9},{%0,%1,%2,%3};"
            : "+f"(c[0]),"+f"(c[1]),"+f"(c[2]),"+f"(c[3])
            : "r"(a[0]),"r"(a[1]),"r"(a[2]),"r"(a[3]),"r"(b[0]),"r"(b[1]));
    else
        asm volatile("mma.sync.aligned.m16n8k16.row.col.f32.bf16.bf16.f32 "
            "{%0,%1,%2,%3},{%4,%5,%6,%7},{%8,%9},{%0,%1,%2,%3};"
            : "+f"(c[0]),"+f"(c[1]),"+f"(c[2]),"+f"(c[3])
            : "r"(a[0]),"r"(a[1]),"r"(a[2]),"r"(a[3]),"r"(b[0]),"r"(b[1]));
}
__device__ __forceinline__ void cpa16(uint32_t dst, const void* src){
    asm volatile("cp.async.cg.shared.global [%0], [%1], 16;" :: "r"(dst), "l"(src));
}
__device__ __forceinline__ void cpa_commit(){ asm volatile("cp.async.commit_group;"); }
template<int N_> __device__ __forceinline__ void cpa_wait(){ asm volatile("cp.async.wait_group %0;"::"n"(N_)); }

__device__ __forceinline__ void split2(float v, __nv_bfloat16& h, __nv_bfloat16& l){
    h = __float2bfloat16(v);
    l = __float2bfloat16(v - __bfloat162float(h));
}

// ---------------- tensor-core GEMM, 4-stage cp.async pipeline ----------------
// BM=128, BN=128, BK=32, 256 threads (8 warps: 2x4), warp tile 64x32.
// TRANSB=false: B is [K,N] row-major (ldb = N). TRANSB=true: B is [N,K] row-major.
// HALF: operands fp16 (else bf16). Pointers are 2-byte elements either way.
// MODE 0: fp32 C = acc + bias[n]
// MODE 2: fp32 C = acc * alpha
// MODE 3: sg = sigmoid(acc+bias); C = sg*E1 + (1-sg)*E2
#define BMt 128
#define BNt 128
#define BKt 32
#define ASTR 40
#define BSTRNN 136
#define NSTAGE 4

template<bool TRANSB, int MODE, bool HALF>
__global__ void __launch_bounds__(256)
mma_gemm(const __nv_bfloat16* __restrict__ A, const __nv_bfloat16* __restrict__ B,
         const float* __restrict__ bias, const float* __restrict__ E1,
         const float* __restrict__ E2, void* __restrict__ Cptr,
         int K, int N, int lda, int ldb, long sA, long sB, long sC, float alpha)
{
    constexpr int ASTAGE = BMt*ASTR*2;
    constexpr int BSTAGE = TRANSB ? (BNt*ASTR*2) : (BKt*BSTRNN*2);
    extern __shared__ char sm[];
    const uint32_t aBase = s2u(sm);
    const uint32_t bBase = aBase + NSTAGE*ASTAGE;

    const int tid  = threadIdx.x;
    const int lane = tid & 31;
    const int warp = tid >> 5;
    const int wm = warp & 1;
    const int wn = warp >> 1;
    const int m0 = blockIdx.y * BMt;
    const int n0 = blockIdx.x * BNt;

    const __nv_bfloat16* Ab = A + blockIdx.z*sA + (long)m0*lda;
    const __nv_bfloat16* Bb = TRANSB ? (B + blockIdx.z*sB + (long)n0*ldb) : (B + n0);

    float acc[4][4][4];
#pragma unroll
    for (int i=0;i<4;i++)
#pragma unroll
        for (int j=0;j<4;j++)
#pragma unroll
            for (int h=0;h<4;h++) acc[i][j][h] = 0.f;

    auto copyA = [&](int st, int k0){
        uint32_t base = aBase + st*ASTAGE;
#pragma unroll
        for (int l=0;l<2;l++){
            int id = tid + l*256; int r = id>>2; int c = (id&3)*8;
            cpa16(base + (r*ASTR + c)*2, Ab + (long)r*lda + k0 + c);
        }
    };
    auto copyB = [&](int st, int k0){
        uint32_t base = bBase + st*BSTAGE;
        if (TRANSB){
#pragma unroll
            for (int l=0;l<2;l++){
                int id = tid + l*256; int r = id>>2; int c = (id&3)*8;
                cpa16(base + (r*ASTR + c)*2, Bb + (long)r*ldb + k0 + c);
            }
        } else {
#pragma unroll
            for (int l=0;l<2;l++){
                int id = tid + l*256; int r = id>>4; int c = (id&15)*8;
                cpa16(base + (r*BSTRNN + c)*2, Bb + (long)(k0+r)*ldb + c);
            }
        }
    };

    const int nt = K / BKt;
#pragma unroll
    for (int s=0; s<NSTAGE-1; s++){
        copyA(s, s*BKt); copyB(s, s*BKt); cpa_commit();
    }

    int buf = 0;
    for (int t = 0; t < nt; t++){
        cpa_wait<NSTAGE-2>();
        __syncthreads();
        const uint32_t aS = aBase + buf*ASTAGE;
        const uint32_t bS = bBase + buf*BSTAGE;
#pragma unroll
        for (int ks=0; ks<2; ks++){
            uint32_t af[4][4];
#pragma unroll
            for (int mi=0; mi<4; mi++){
                int row = wm*64 + mi*16 + (lane&15);
                int col = ks*16 + ((lane>>4)<<3);
                ldsm4(af[mi][0],af[mi][1],af[mi][2],af[mi][3],
                      aS + (row*ASTR + col)*2);
            }
            uint32_t bf[4][2];
            if (TRANSB){
#pragma unroll
                for (int nj=0; nj<2; nj++){
                    int g = lane>>3;
                    int row = wn*32 + nj*16 + ((g>>1)<<3) + (lane&7);
                    int col = ks*16 + ((g&1)<<3);
                    uint32_t r0,r1,r2,r3;
                    ldsm4(r0,r1,r2,r3, bS + (row*ASTR + col)*2);
                    bf[nj*2][0]=r0; bf[nj*2][1]=r1; bf[nj*2+1][0]=r2; bf[nj*2+1][1]=r3;
                }
            } else {
#pragma unroll
                for (int nj=0; nj<2; nj++){
                    int row = ks*16 + (lane&15);
                    int col = wn*32 + nj*16 + ((lane>>4)<<3);
                    uint32_t r0,r1,r2,r3;
                    ldsm4t(r0,r1,r2,r3, bS + (row*BSTRNN + col)*2);
                    bf[nj*2][0]=r0; bf[nj*2][1]=r1; bf[nj*2+1][0]=r2; bf[nj*2+1][1]=r3;
                }
            }
#pragma unroll
            for (int mi=0;mi<4;mi++)
#pragma unroll
                for (int ni=0;ni<4;ni++)
                    mma16816<HALF>(acc[mi][ni], af[mi], bf[ni]);
        }
        int tn = t + NSTAGE-1;
        if (tn < nt){
            int st = buf + NSTAGE-1; if (st >= NSTAGE) st -= NSTAGE;
            copyA(st, tn*BKt); copyB(st, tn*BKt);
        }
        cpa_commit();
        buf = (buf+1 == NSTAGE) ? 0 : buf+1;
    }

    const long cb = blockIdx.z*sC;
#pragma unroll
    for (int mi=0;mi<4;mi++){
#pragma unroll
        for (int ni=0;ni<4;ni++){
#pragma unroll
            for (int h=0; h<2; h++){
                int row = m0 + wm*64 + mi*16 + (lane>>2) + h*8;
                int col = n0 + wn*32 + ni*8 + (lane&3)*2;
                long idx = cb + (long)row*N + col;
                float v0 = acc[mi][ni][h*2], v1 = acc[mi][ni][h*2+1];
                if (MODE == 0){
                    float* C = (float*)Cptr;
                    C[idx]   = v0 + bias[col];
                    C[idx+1] = v1 + bias[col+1];
                } else if (MODE == 2){
                    float2 o; o.x = v0*alpha; o.y = v1*alpha;
                    *reinterpret_cast<float2*>((float*)Cptr + idx) = o;
                } else {
                    float* C = (float*)Cptr;
                    float p0 = v0 + bias[col],   p1 = v1 + bias[col+1];
                    float s0 = 1.f/(1.f+expf(-p0)), s1 = 1.f/(1.f+expf(-p1));
                    C[idx]   = s0*E1[idx]   + (1.f-s0)*E2[idx];
                    C[idx+1] = s1*E1[idx+1] + (1.f-s1)*E2[idx+1];
                }
            }
        }
    }
}

// ---------------- split x: bf16x3 (stride K3) + fp16 into xcat (stride K2) ----------------
__global__ void __launch_bounds__(256)
split_x_kernel(const float* __restrict__ in, __nv_bfloat16* __restrict__ xs,
               __half* __restrict__ xcat)
{
    long i = (long)blockIdx.x*256 + threadIdx.x;
    int m = (int)(i >> 10), k = (int)(i & 1023);
    float v = in[i];
    __nv_bfloat16 h,l; split2(v,h,l);
    long ob = (long)m*K3 + k;
    xs[ob] = h; xs[ob+1024] = l; xs[ob+2048] = h;
    xcat[(long)m*K2 + k] = __float2half(v);
}

// ---------------- weight split (bf16 [K,N] -> [3K,N] hi;hi;lo) for wq,wk ----------------
struct W2 { const float* in[2]; __nv_bfloat16* out[2]; };
__global__ void __launch_bounds__(256)
split_w_kernel(W2 p)
{
    int w = blockIdx.z;
    long i = (long)blockIdx.x*256 + threadIdx.x;
    float v = p.in[w][i];
    __nv_bfloat16 h,l; split2(v,h,l);
    p.out[w][i] = h;
    p.out[w][i + (long)1024*1024] = h;
    p.out[w][i + (long)2*1024*1024] = l;
}

// ---------------- generic fp32 -> fp16 convert ----------------
__global__ void __launch_bounds__(256)
conv_f2h(const float* __restrict__ in, __half* __restrict__ out)
{
    long i = (long)blockIdx.x*256 + threadIdx.x;
    out[i] = __float2half(in[i]);
}
__global__ void __launch_bounds__(256)
conv_qk(const float* __restrict__ q, const float* __restrict__ k,
        __half* __restrict__ qh, __half* __restrict__ kh)
{
    long i = (long)blockIdx.x*256 + threadIdx.x;
    qh[i] = __float2half(q[i]);
    kh[i] = __float2half(k[i]);
}

// ---------------- top-k helpers ----------------
__device__ __forceinline__ void ins4(float v, int id, float tv[4], int ti[4]) {
    if (v <= tv[3]) return;
    if (v > tv[0]) { tv[3]=tv[2]; ti[3]=ti[2]; tv[2]=tv[1]; ti[2]=ti[1];
                     tv[1]=tv[0]; ti[1]=ti[0]; tv[0]=v; ti[0]=id; }
    else if (v > tv[1]) { tv[3]=tv[2]; ti[3]=ti[2]; tv[2]=tv[1]; ti[2]=ti[1]; tv[1]=v; ti[1]=id; }
    else if (v > tv[2]) { tv[3]=tv[2]; ti[3]=ti[2]; tv[2]=v; ti[2]=id; }
    else { tv[3]=v; ti[3]=id; }
}
__device__ __forceinline__ void ins8(float v, int id, float* tv, int* ti) {
    if (v <= tv[7]) return;
    tv[7] = v; ti[7] = id;
#pragma unroll
    for (int j=7; j>0; j--){
        if (tv[j] > tv[j-1]){
            float tf=tv[j]; tv[j]=tv[j-1]; tv[j-1]=tf;
            int tii=ti[j]; ti[j]=ti[j-1]; ti[j-1]=tii;
        }
    }
}

// ---------------- top-8 approx + exact fp32 rescue -> top-4 ----------------
__global__ void __launch_bounds__(128)
topk_rescue(const float* __restrict__ logits, const float* __restrict__ q,
            const float* __restrict__ k, float* __restrict__ topv, int* __restrict__ topi)
{
    const int m = blockIdx.x;
    const int tid = threadIdx.x;
    const float* p = logits + (long)m * Sdim;

    float tv[8]; int ti[8];
#pragma unroll
    for (int j=0;j<8;j++){ tv[j]=-1e30f; ti[j]=-1; }
    for (int j = tid; j < Sdim; j += 128) ins8(p[j], j, tv, ti);

    __shared__ float sv[128*8];
    __shared__ int   si[128*8];
#pragma unroll
    for (int j=0;j<8;j++){ sv[tid*8+j]=tv[j]; si[tid*8+j]=ti[j]; }
    __syncthreads();

    if (tid < 32){
        float mv[8]; int mi[8];
#pragma unroll
        for (int j=0;j<8;j++){ mv[j]=-1e30f; mi[j]=-1; }
        for (int s=0;s<4;s++){
            int base = (tid + s*32)*8;
#pragma unroll
            for (int j=0;j<8;j++) ins8(sv[base+j], si[base+j], mv, mi);
        }
#pragma unroll
        for (int j=0;j<8;j++){ sv[tid*8+j]=mv[j]; si[tid*8+j]=mi[j]; }
    }
    __syncthreads();

    __shared__ int cands[8];
    if (tid == 0){
        float rv[8]; int ri[8];
#pragma unroll
        for (int j=0;j<8;j++){ rv[j]=-1e30f; ri[j]=-1; }
        for (int c=0;c<32*8;c++) ins8(sv[c], si[c], rv, ri);
#pragma unroll
        for (int j=0;j<8;j++) cands[j] = ri[j];
    }
    __syncthreads();

    __shared__ float qrow[Hdim];
    const float* qr = q + (long)m*Hdim;
    for (int j = tid; j < Hdim; j += 128) qrow[j] = qr[j];
    __syncthreads();

    const int b = m >> 12;
    const int warp = tid >> 5, lane = tid & 31;
    __shared__ float exact[8];
#pragma unroll
    for (int cc=0; cc<2; cc++){
        int c = warp*2 + cc;
        const float* kr = k + ((long)b*Sdim + cands[c])*Hdim;
        float s = 0.f;
        for (int j = lane; j < Hdim; j += 32) s += qrow[j]*kr[j];
#pragma unroll
        for (int o=16;o>0;o>>=1) s += __shfl_down_sync(0xffffffffu, s, o);
        if (lane == 0) exact[c] = s * INV_SCALE;
    }
    __syncthreads();

    if (tid == 0){
        float rv[4] = {-1e30f,-1e30f,-1e30f,-1e30f};
        int   ri[4] = {-1,-1,-1,-1};
#pragma unroll
        for (int c=0;c<8;c++) ins4(exact[c], cands[c], rv, ri);
#pragma unroll
        for (int j=0;j<4;j++){ topv[m*4+j]=rv[j]; topi[m*4+j]=ri[j]; }
    }
}

// ---------------- softmax + gather-weighted V -> fp16 routed ----------------
__global__ void __launch_bounds__(256)
route_kernel(const float* __restrict__ v, const float* __restrict__ topv,
             const int* __restrict__ topi, const float* __restrict__ temp,
             __half* __restrict__ rh)
{
    const int m = blockIdx.x;
    const int b = m >> 12;
    const float t = temp[0];
    float v0 = topv[m*4+0], v1 = topv[m*4+1], v2 = topv[m*4+2], v3 = topv[m*4+3];
    float mx = fmaxf(fmaxf(v0,v1), fmaxf(v2,v3));
    float e0 = expf((v0-mx)/t), e1 = expf((v1-mx)/t);
    float e2 = expf((v2-mx)/t), e3 = expf((v3-mx)/t);
    float inv = 1.f/(e0+e1+e2+e3);
    e0*=inv; e1*=inv; e2*=inv; e3*=inv;

    const float* vb = v + (long)b*Sdim*Hdim;
    int i0=topi[m*4+0], i1=topi[m*4+1], i2=topi[m*4+2], i3=topi[m*4+3];
    const float4* r0 = reinterpret_cast<const float4*>(vb + (long)i0*Hdim);
    const float4* r1 = reinterpret_cast<const float4*>(vb + (long)i1*Hdim);
    const float4* r2 = reinterpret_cast<const float4*>(vb + (long)i2*Hdim);
    const float4* r3 = reinterpret_cast<const float4*>(vb + (long)i3*Hdim);

    int c = threadIdx.x;
    float4 a = r0[c], bb = r1[c], cc = r2[c], dd = r3[c];
    float o[4];
    o[0] = e0*a.x + e1*bb.x + e2*cc.x + e3*dd.x;
    o[1] = e0*a.y + e1*bb.y + e2*cc.y + e3*dd.y;
    o[2] = e0*a.z + e1*bb.z + e2*cc.z + e3*dd.z;
    o[3] = e0*a.w + e1*bb.w + e2*cc.w + e3*dd.w;
    long ob = (long)m*Hdim + c*4;
#pragma unroll
    for (int j=0;j<4;j++) rh[ob+j] = __float2half(o[j]);
}

// ---------------- LayerNorm (+gelu) -> optional fp32 + fp16 out ----------------
template<int GELU>
__global__ void __launch_bounds__(256)
ln_kernel(const float* __restrict__ in, const float* __restrict__ g,
          const float* __restrict__ b, float* __restrict__ outf,
          __half* __restrict__ outh, int ostride)
{
    const int m = blockIdx.x;
    const int c = threadIdx.x;
    float4 x4 = reinterpret_cast<const float4*>(in + (long)m*Hdim)[c];
    float s  = x4.x + x4.y + x4.z + x4.w;
    float ss = x4.x*x4.x + x4.y*x4.y + x4.z*x4.z + x4.w*x4.w;
#pragma unroll
    for (int o=16;o>0;o>>=1){
        s  += __shfl_down_sync(0xffffffffu, s,  o);
        ss += __shfl_down_sync(0xffffffffu, ss, o);
    }
    __shared__ float red[2][8];
    int warp = c>>5, lane = c&31;
    if (lane==0){ red[0][warp]=s; red[1][warp]=ss; }
    __syncthreads();
    if (c==0){
        float S_=0.f, SS_=0.f;
#pragma unroll
        for (int w=0;w<8;w++){ S_+=red[0][w]; SS_+=red[1][w]; }
        red[0][0]=S_; red[1][0]=SS_;
    }
    __syncthreads();
    float mu  = red[0][0]*(1.f/Hdim);
    float var = red[1][0]*(1.f/Hdim) - mu*mu;
    float rsd = rsqrtf(var + LNEPS);
    float4 g4 = reinterpret_cast<const float4*>(g)[c];
    float4 b4 = reinterpret_cast<const float4*>(b)[c];
    float y[4];
    y[0] = (x4.x-mu)*rsd*g4.x + b4.x;
    y[1] = (x4.y-mu)*rsd*g4.y + b4.y;
    y[2] = (x4.z-mu)*rsd*g4.z + b4.z;
    y[3] = (x4.w-mu)*rsd*g4.w + b4.w;
    if (GELU){
#pragma unroll
        for (int j=0;j<4;j++) y[j] = 0.5f*y[j]*(1.f + erff(y[j]*0.70710678118f));
    }
    if (outf){
        float4 yo; yo.x=y[0]; yo.y=y[1]; yo.z=y[2]; yo.w=y[3];
        reinterpret_cast<float4*>(outf + (long)m*Hdim)[c] = yo;
    }
    long ob = (long)m*ostride + c*4;
#pragma unroll
    for (int j=0;j<4;j++) outh[ob+j] = __float2half(y[j]);
}

// ---------------- launch ----------------
extern "C" void kernel_launch(void* const* d_in, const int* in_sizes, int n_in,
                              void* d_out, int out_size)
{
    const float* x    = (const float*)d_in[0];
    const float* Wq   = (const float*)d_in[1];
    const float* bq   = (const float*)d_in[2];
    const float* Wk   = (const float*)d_in[3];
    const float* bk   = (const float*)d_in[4];
    const float* Wv   = (const float*)d_in[5];
    const float* bv   = (const float*)d_in[6];
    const float* Wc   = (const float*)d_in[7];
    const float* bc   = (const float*)d_in[8];
    const float* ln_g = (const float*)d_in[9];
    const float* ln_b = (const float*)d_in[10];
    const float* Wg1  = (const float*)d_in[11];
    const float* bg1  = (const float*)d_in[12];
    const float* gln_g= (const float*)d_in[13];
    const float* gln_b= (const float*)d_in[14];
    const float* Wg2  = (const float*)d_in[15];
    const float* bg2  = (const float*)d_in[16];
    const float* temp = (const float*)d_in[17];
    float* out = (float*)d_out;

    __nv_bfloat16 *xs_p, *wqk_p;
    __half *xcat_p, *qh_p, *kh_p, *rh_p, *hs_p, *wh_p, *wg1h_p;
    float *q_p, *k_p, *v_p, *logits_p, *topv_p, *cpre_p, *comb_p, *hpre_p;
    int *topi_p;
    cudaGetSymbolAddress((void**)&xs_p,    g_xs);
    cudaGetSymbolAddress((void**)&xcat_p,  g_xcat);
    cudaGetSymbolAddress((void**)&q_p,     g_q);
    cudaGetSymbolAddress((void**)&k_p,     g_k);
    cudaGetSymbolAddress((void**)&v_p,     g_v);
    cudaGetSymbolAddress((void**)&qh_p,    g_qh);
    cudaGetSymbolAddress((void**)&kh_p,    g_kh);
    cudaGetSymbolAddress((void**)&logits_p,g_logits);
    cudaGetSymbolAddress((void**)&topv_p,  g_topv);
    cudaGetSymbolAddress((void**)&topi_p,  g_topi);
    cudaGetSymbolAddress((void**)&rh_p,    g_rh);
    cudaGetSymbolAddress((void**)&cpre_p,  g_cpre);
    cudaGetSymbolAddress((void**)&comb_p,  g_comb);
    cudaGetSymbolAddress((void**)&hpre_p,  g_hpre);
    cudaGetSymbolAddress((void**)&hs_p,    g_hs);
    cudaGetSymbolAddress((void**)&wqk_p,   g_wqk);
    cudaGetSymbolAddress((void**)&wh_p,    g_wh);
    cudaGetSymbolAddress((void**)&wg1h_p,  g_wg1h);

    __nv_bfloat16 *wq_p = wqk_p, *wk_p = wqk_p + (long)K3*Hdim;
    __half *wv_p = wh_p, *wc_p = wh_p + (long)Hdim*Hdim, *wg2_p = wh_p + 2*(long)Hdim*Hdim;

    // prep
    split_x_kernel<<<MTOT*Hdim/256, 256>>>(x, xs_p, xcat_p);
    W2 wp; wp.in[0]=Wq; wp.out[0]=wq_p; wp.in[1]=Wk; wp.out[1]=wk_p;
    split_w_kernel<<<dim3(Hdim*Hdim/256,1,2), 256>>>(wp);
    conv_f2h<<<Hdim*Hdim/256, 256>>>(Wv, wv_p);
    conv_f2h<<<Hdim*Hdim/256, 256>>>(Wc, wc_p);
    conv_f2h<<<Hdim*Hdim/256, 256>>>(Wg2, wg2_p);
    conv_f2h<<<K2*Hdim/256, 256>>>(Wg1, wg1h_p);

    dim3 gNN(Hdim/BNt, MTOT/BMt, 1);       // (8, 64)
    dim3 gNT(Sdim/BNt, Sdim/BMt, Bdim);    // (32, 32, 2)

    const int smemNN = NSTAGE*(BMt*ASTR*2 + BKt*BSTRNN*2);   // 75776
    const int smemNT = NSTAGE*(BMt*ASTR*2 + BNt*ASTR*2);     // 81920

    cudaFuncSetAttribute((const void*)mma_gemm<false,0,false>, cudaFuncAttributeMaxDynamicSharedMemorySize, smemNN);
    cudaFuncSetAttribute((const void*)mma_gemm<false,0,true>,  cudaFuncAttributeMaxDynamicSharedMemorySize, smemNN);
    cudaFuncSetAttribute((const void*)mma_gemm<false,3,true>,  cudaFuncAttributeMaxDynamicSharedMemorySize, smemNN);
    cudaFuncSetAttribute((const void*)mma_gemm<true,2,true>,   cudaFuncAttributeMaxDynamicSharedMemorySize, smemNT);

    // q, k (bf16x3, K=3072, fp32 out)
    mma_gemm<false,0,false><<<gNN,256,smemNN>>>(xs_p, wq_p, bq, nullptr, nullptr, q_p, K3, Hdim, K3, Hdim, 0,0,0, 1.f);
    mma_gemm<false,0,false><<<gNN,256,smemNN>>>(xs_p, wk_p, bk, nullptr, nullptr, k_p, K3, Hdim, K3, Hdim, 0,0,0, 1.f);

    // v (fp16 single pass, K=1024)
    mma_gemm<false,0,true><<<gNN,256,smemNN>>>((const __nv_bfloat16*)xcat_p, (const __nv_bfloat16*)wv_p,
                                   bv, nullptr, nullptr, v_p, Hdim, Hdim, K2, Hdim, 0,0,0, 1.f);

    // fp16 copies of q,k for approx logits
    conv_qk<<<MTOT*Hdim/256, 256>>>(q_p, k_p, qh_p, kh_p);

    // approx logits = qh @ kh^T / 8  (fp16 single pass, K=1024)
    mma_gemm<true,2,true><<<gNT,256,smemNT>>>((const __nv_bfloat16*)qh_p, (const __nv_bfloat16*)kh_p,
                                  nullptr, nullptr, nullptr, logits_p,
                                  Hdim, Sdim, Hdim, Hdim,
                                  (long)Sdim*Hdim, (long)Sdim*Hdim, (long)Sdim*Sdim, INV_SCALE);

    // top-8 approx -> exact fp32 rescue -> top-4
    topk_rescue<<<MTOT,128>>>(logits_p, q_p, k_p, topv_p, topi_p);
    route_kernel<<<MTOT,256>>>(v_p, topv_p, topi_p, temp, rh_p);

    // combined = LN(routed @ Wc + bc); fp16 into xcat second half
    mma_gemm<false,0,true><<<gNN,256,smemNN>>>((const __nv_bfloat16*)rh_p, (const __nv_bfloat16*)wc_p,
                                   bc, nullptr, nullptr, cpre_p, Hdim, Hdim, Hdim, Hdim, 0,0,0, 1.f);
    ln_kernel<0><<<MTOT,256>>>(cpre_p, ln_g, ln_b, comb_p, xcat_p + Hdim, K2);

    // hpre = [x|combined] @ Wg1 + bg1  (fp16, K=2048)
    mma_gemm<false,0,true><<<gNN,256,smemNN>>>((const __nv_bfloat16*)xcat_p, (const __nv_bfloat16*)wg1h_p,
                                   bg1, nullptr, nullptr, hpre_p, K2, Hdim, K2, Hdim, 0,0,0, 1.f);

    // h = gelu(LN(hpre))
    ln_kernel<1><<<MTOT,256>>>(hpre_p, gln_g, gln_b, nullptr, hs_p, Hdim);

    // out = sigmoid(h @ Wg2 + bg2) * combined + (1-s) * x
    mma_gemm<false,3,true><<<gNN,256,smemNN>>>((const __nv_bfloat16*)hs_p, (const __nv_bfloat16*)wg2_p,
                                   bg2, comb_p, x, out, Hdim, Hdim, Hdim, Hdim, 0,0,0, 1.f);
}